// round 11
// baseline (speedup 1.0000x reference)
#include <cuda_runtime.h>
#include <cuda_fp16.h>
#include <math.h>
#include <stdint.h>

// ---------------- problem-size constants ----------------
#define NMAX 100000
#define EMAX 1600000

// ---------------- device scratch ----------------
__device__ __align__(16) __half g_gh[(size_t)NMAX * 384];   // fp16: x @ W_hh^T + b_hh
__device__ __align__(16) __half g_gi[(size_t)NMAX * 384];   // fp16: agg_max @ W_ih^T + b_ih
__device__ __align__(16) __half g_xxi[(size_t)NMAX * 256];  // interleaved fp16 [x4|xi4] (gather)
__device__ __align__(16) __half g_xf[(size_t)NMAX * 128];   // plain fp16 x (xi/gh A-side)
__device__ __align__(16) __half g_am[(size_t)NMAX * 128];   // fp16 agg_max (exact)
__device__ __align__(16) __half g_cat[(size_t)NMAX * 256];  // fp16 [agg_sum | rnn_out]
__device__ __align__(16) __half g_hf[(size_t)NMAX * 128];   // fp16 merge out
__device__ __align__(16) __half g_tf[(size_t)NMAX * 256];   // fp16 relu(W1...)

__device__ __align__(16) __half g_wf_h[212992];  // fp16 weight hi (aff,ih,hh,mg,w1,w2)
__device__ __align__(16) __half g_wf_l[212992];  // fp16 weight lo

__device__ int g_cnt[NMAX];
__device__ int g_rowstart[NMAX];
__device__ int g_cursor[NMAX];
__device__ int g_col[EMAX];
__device__ int g_bsum[256];
__device__ int g_boff[256];
__device__ float g_bnsum[128];
__device__ float g_bnsq[128];

// fp16 weight offsets (elements)
#define F16_AFF 0
#define F16_IH  16384
#define F16_HH  65536
#define F16_MG  114688
#define F16_W1  147456
#define F16_W2  180224

// ---------------- low-level helpers (plain sm_80-class PTX) ----------------
__device__ __forceinline__ uint32_t smem_u32(const void* p) {
    uint32_t a;
    asm("{ .reg .u64 t; cvta.to.shared.u64 t, %1; cvt.u32.u64 %0, t; }" : "=r"(a) : "l"(p));
    return a;
}
__device__ __forceinline__ void cpasync16(uint32_t dst, const void* src) {
    asm volatile("cp.async.cg.shared.global [%0], [%1], 16;" :: "r"(dst), "l"(src));
}
__device__ __forceinline__ void cp_commit() {
    asm volatile("cp.async.commit_group;" ::: "memory");
}
__device__ __forceinline__ void cp_wait1() {
    asm volatile("cp.async.wait_group 1;" ::: "memory");
}
__device__ __forceinline__ void cp_wait0() {
    asm volatile("cp.async.wait_group 0;" ::: "memory");
}
__device__ __forceinline__ void ldsm4(uint32_t* r, uint32_t addr) {
    asm volatile("ldmatrix.sync.aligned.m8n8.x4.shared.b16 {%0,%1,%2,%3}, [%4];"
                 : "=r"(r[0]), "=r"(r[1]), "=r"(r[2]), "=r"(r[3]) : "r"(addr));
}
__device__ __forceinline__ void mma_f16(float* d, const uint32_t* a, const uint32_t* b) {
    asm volatile(
        "mma.sync.aligned.m16n8k16.row.col.f32.f16.f16.f32 "
        "{%0,%1,%2,%3}, {%4,%5,%6,%7}, {%8,%9}, {%0,%1,%2,%3};"
        : "+f"(d[0]), "+f"(d[1]), "+f"(d[2]), "+f"(d[3])
        : "r"(a[0]), "r"(a[1]), "r"(a[2]), "r"(a[3]), "r"(b[0]), "r"(b[1]));
}

// ---------------- split helpers ----------------
__device__ __forceinline__ void f16_split1(float v, unsigned short& hb, unsigned short& lb) {
    __half h = __float2half_rn(v);
    float hf = __half2float(h);
    __half l = __float2half_rn(v - hf);
    hb = __half_as_ushort(h);
    lb = __half_as_ushort(l);
}
__device__ __forceinline__ void f16_split_store4(__half* ph, __half* pl, float4 v) {
    unsigned short h0, h1, h2, h3, l0, l1, l2, l3;
    f16_split1(v.x, h0, l0); f16_split1(v.y, h1, l1);
    f16_split1(v.z, h2, l2); f16_split1(v.w, h3, l3);
    *(uint2*)ph = make_uint2((uint32_t)h0 | ((uint32_t)h1 << 16), (uint32_t)h2 | ((uint32_t)h3 << 16));
    *(uint2*)pl = make_uint2((uint32_t)l0 | ((uint32_t)l1 << 16), (uint32_t)l2 | ((uint32_t)l3 << 16));
}
__device__ __forceinline__ void f16_store4(__half* p, float4 v) {
    __half2 a = __floats2half2_rn(v.x, v.y);
    __half2 b = __floats2half2_rn(v.z, v.w);
    *(uint2*)p = make_uint2(*(uint32_t*)&a, *(uint32_t*)&b);
}

// x: plain fp16 copy + interleaved fp16 x-slots of xxi
__global__ void split_kernel(const float* __restrict__ in, int n4) {
    int i = blockIdx.x * blockDim.x + threadIdx.x;
    if (i >= n4) return;
    float4 v = ((const float4*)in)[i];
    f16_store4(g_xf + (size_t)i * 4, v);
    int node = i >> 5;
    int c4 = i & 31;
    __half2 f0 = __floats2half2_rn(v.x, v.y);
    __half2 f1 = __floats2half2_rn(v.z, v.w);
    *(uint2*)(g_xxi + (size_t)node * 256 + c4 * 8) = make_uint2(*(uint32_t*)&f0, *(uint32_t*)&f1);
}

// Weights -> fp16 hi/lo pairs. float4 idx ranges:
// aff [0,4096) ih [4096,16384) hh [16384,28672) mg [28672,36864) w1 [36864,45056) w2 [45056,53248)
__global__ void split_weights_kernel(const float* __restrict__ Waff, const float* __restrict__ Wih,
                                     const float* __restrict__ Whh, const float* __restrict__ Wmg,
                                     const float* __restrict__ W1, const float* __restrict__ W2) {
    int i = blockIdx.x * blockDim.x + threadIdx.x;
    if (i >= 53248) return;
    const float* src; int base;
    if (i < 4096)       { src = Waff; base = 0; }
    else if (i < 16384) { src = Wih;  base = 4096; }
    else if (i < 28672) { src = Whh;  base = 16384; }
    else if (i < 36864) { src = Wmg;  base = 28672; }
    else if (i < 45056) { src = W1;   base = 36864; }
    else                { src = W2;   base = 45056; }
    float4 v = ((const float4*)src)[i - base];
    f16_split_store4(g_wf_h + (size_t)i * 4, g_wf_l + (size_t)i * 4, v);
}

// ---------------- init ----------------
__global__ void zero_init_kernel(int n) {
    int i = blockIdx.x * blockDim.x + threadIdx.x;
    if (i < n) g_cnt[i] = 0;
    if (i < 128) { g_bnsum[i] = 0.f; g_bnsq[i] = 0.f; }
}

// ---------------- CSR build ----------------
__global__ void count_kernel(const int* __restrict__ edges, int E) {
    int e = blockIdx.x * blockDim.x + threadIdx.x;
    if (e >= E) return;
    atomicAdd(&g_cnt[edges[E + e]], 1);
}
__global__ void scan1_kernel(int n) {
    __shared__ int sh[1024];
    int tid = threadIdx.x;
    int i = blockIdx.x * 1024 + tid;
    int v = (i < n) ? g_cnt[i] : 0;
    sh[tid] = v;
    __syncthreads();
    for (int off = 1; off < 1024; off <<= 1) {
        int t = (tid >= off) ? sh[tid - off] : 0;
        __syncthreads();
        sh[tid] += t;
        __syncthreads();
    }
    if (i < n) g_rowstart[i] = sh[tid] - v;
    if (tid == 1023) g_bsum[blockIdx.x] = sh[1023];
}
__global__ void scan2_kernel(int nb) {
    __shared__ int sh[128];
    int t = threadIdx.x;
    int v = (t < nb) ? g_bsum[t] : 0;
    sh[t] = v;
    __syncthreads();
    for (int off = 1; off < 128; off <<= 1) {
        int u = (t >= off) ? sh[t - off] : 0;
        __syncthreads();
        sh[t] += u;
        __syncthreads();
    }
    if (t < nb) g_boff[t] = sh[t] - v;
}
__global__ void scan3_kernel(int n) {
    int i = blockIdx.x * blockDim.x + threadIdx.x;
    if (i < n) {
        int v = g_rowstart[i] + g_boff[i >> 10];
        g_rowstart[i] = v;
        g_cursor[i] = v;
    }
}
__global__ void fill_kernel(const int* __restrict__ edges, int E) {
    int e = blockIdx.x * blockDim.x + threadIdx.x;
    if (e >= E) return;
    int src = edges[e];
    int dst = edges[E + e];
    int pos = atomicAdd(&g_cursor[dst], 1);
    g_col[pos] = src;
}

__device__ __forceinline__ uint32_t sw128(uint32_t r, uint32_t u) {
    return r * 128u + ((u ^ (r & 7u)) << 4);
}

// ---------------- fp16 GEMM: D = A_f16 @ (Bh[+Bl])^T + bias ----------------
// Bl==nullptr -> single-B (1 MMA/step), stage 32KB. Bl!=nullptr -> 2-term, stage 48KB.
// stage_bytes passed to match; dynamic smem = 1024 + 2*stage_bytes.
#define GEMM2_SMEM_MAX (1024 + 2 * 49152)

__global__ __launch_bounds__(256, 2)
void hmma_gemm_f16(const __half* __restrict__ A,
                   const __half* __restrict__ Bh, const __half* __restrict__ Bl,
                   const float* __restrict__ bias,
                   float* __restrict__ Cf, __half* __restrict__ Cf16, int c16il,
                   int M, int Ntot, int K, int relu, int bnred, uint32_t stage_bytes,
                   const float* __restrict__ resid, const float* __restrict__ eps_ptr)
{
    extern __shared__ char dsm[];
    uint32_t sb0 = smem_u32(dsm);
    uint32_t base0 = (sb0 + 1023u) & ~1023u;
    char* p0 = dsm + (base0 - sb0);

    int tid = threadIdx.x;
    int lane = tid & 31;
    int wid = tid >> 5;
    int wm = wid >> 2;
    int wn = wid & 3;
    int bm = blockIdx.y * 128, bn = blockIdx.x * 128;

    float acc[4][4][4];
#pragma unroll
    for (int i = 0; i < 4; i++)
#pragma unroll
        for (int j = 0; j < 4; j++)
#pragma unroll
            for (int k = 0; k < 4; k++) acc[i][j][k] = 0.f;

    const int NSt = K >> 6;

    auto load_stage = [&](int s) {
        uint32_t buf = base0 + (uint32_t)(s & 1) * stage_bytes;
        int kc = s * 64;
#pragma unroll
        for (int i = 0; i < 4; i++) {
            int idx = tid + i * 256;
            uint32_t r = (uint32_t)(idx >> 3);
            uint32_t u = (uint32_t)(idx & 7);
            int gr = bm + (int)r; if (gr > M - 1) gr = M - 1;
            cpasync16(buf + sw128(r, u), A + (size_t)gr * K + kc + u * 8);
        }
#pragma unroll
        for (int i = 0; i < 4; i++) {
            int idx = tid + i * 256;
            uint32_t r = (uint32_t)(idx >> 3);
            uint32_t u = (uint32_t)(idx & 7);
            int gr = bn + (int)r; if (gr > Ntot - 1) gr = Ntot - 1;
            cpasync16(buf + 16384u + sw128(r, u), Bh + (size_t)gr * K + kc + u * 8);
        }
        if (Bl) {
#pragma unroll
            for (int i = 0; i < 4; i++) {
                int idx = tid + i * 256;
                uint32_t r = (uint32_t)(idx >> 3);
                uint32_t u = (uint32_t)(idx & 7);
                int gr = bn + (int)r; if (gr > Ntot - 1) gr = Ntot - 1;
                cpasync16(buf + 32768u + sw128(r, u), Bl + (size_t)gr * K + kc + u * 8);
            }
        }
        cp_commit();
    };

    load_stage(0);
    for (int s = 0; s < NSt; s++) {
        if (s + 1 < NSt) { load_stage(s + 1); cp_wait1(); }
        else cp_wait0();
        __syncthreads();
        uint32_t buf = base0 + (uint32_t)(s & 1) * stage_bytes;
#pragma unroll
        for (int ks = 0; ks < 4; ks++) {
            uint32_t bh[4][2], bl[4][2];
#pragma unroll
            for (int jp = 0; jp < 2; jp++) {
                uint32_t r = (uint32_t)(wn * 32 + jp * 16) + (uint32_t)(lane & 7) + (uint32_t)((lane >> 4) << 3);
                uint32_t u = (uint32_t)(ks * 2 + ((lane >> 3) & 1));
                uint32_t off = sw128(r, u);
                uint32_t t4[4];
                ldsm4(t4, buf + 16384u + off);
                bh[jp * 2][0] = t4[0]; bh[jp * 2][1] = t4[1];
                bh[jp * 2 + 1][0] = t4[2]; bh[jp * 2 + 1][1] = t4[3];
                if (Bl) {
                    ldsm4(t4, buf + 32768u + off);
                    bl[jp * 2][0] = t4[0]; bl[jp * 2][1] = t4[1];
                    bl[jp * 2 + 1][0] = t4[2]; bl[jp * 2 + 1][1] = t4[3];
                }
            }
#pragma unroll
            for (int mi = 0; mi < 4; mi++) {
                uint32_t r = (uint32_t)(wm * 64 + mi * 16) + (uint32_t)(lane & 15);
                uint32_t u = (uint32_t)(ks * 2 + (lane >> 4));
                uint32_t off = sw128(r, u);
                uint32_t af[4];
                ldsm4(af, buf + off);
#pragma unroll
                for (int ni = 0; ni < 4; ni++) {
                    mma_f16(acc[mi][ni], af, bh[ni]);
                    if (Bl) mma_f16(acc[mi][ni], af, bl[ni]);
                }
            }
        }
        __syncthreads();
    }

    // ---------------- epilogue ----------------
    float e = resid ? __ldg(eps_ptr) : 0.f;
    float cs[4][2], cq[4][2];
#pragma unroll
    for (int ni = 0; ni < 4; ni++) { cs[ni][0] = cs[ni][1] = cq[ni][0] = cq[ni][1] = 0.f; }

#pragma unroll
    for (int mi = 0; mi < 4; mi++) {
#pragma unroll
        for (int rr = 0; rr < 2; rr++) {
            int gr = bm + wm * 64 + mi * 16 + (lane >> 2) + rr * 8;
            if (gr >= M) continue;
#pragma unroll
            for (int ni = 0; ni < 4; ni++) {
                int gc = bn + wn * 32 + ni * 8 + (lane & 3) * 2;
                float v0 = acc[mi][ni][rr * 2 + 0];
                float v1 = acc[mi][ni][rr * 2 + 1];
                float2 bv = *(const float2*)(bias + gc);
                v0 += bv.x; v1 += bv.y;
                if (resid) {
                    float2 rv = *(const float2*)(resid + (size_t)gr * Ntot + gc);
                    v0 += e * rv.x; v1 += e * rv.y;
                }
                if (relu) { v0 = fmaxf(v0, 0.f); v1 = fmaxf(v1, 0.f); }
                if (bnred) {
                    cs[ni][0] += v0; cq[ni][0] += v0 * v0;
                    cs[ni][1] += v1; cq[ni][1] += v1 * v1;
                }
                if (Cf) {
                    *(float2*)(Cf + (size_t)gr * Ntot + gc) = make_float2(v0, v1);
                } else {
                    __half2 hv = __floats2half2_rn(v0, v1);
                    if (c16il) {
                        // interleaved xxi: xi pair at node*256 + (gc>>2)*8 + 4 + (gc&3)
                        *(uint32_t*)(Cf16 + (size_t)gr * 256 + ((gc >> 2) << 3) + 4 + (gc & 3)) =
                            *(uint32_t*)&hv;
                    } else {
                        *(uint32_t*)(Cf16 + (size_t)gr * Ntot + gc) = *(uint32_t*)&hv;
                    }
                }
            }
        }
    }

    if (bnred) {
        float* bsum = (float*)p0;
        float* bsq  = bsum + 128;
        __syncthreads();
        if (tid < 256) ((float*)p0)[tid] = 0.f;
        __syncthreads();
#pragma unroll
        for (int ni = 0; ni < 4; ni++) {
#pragma unroll
            for (int h = 0; h < 2; h++) {
                int col = wn * 32 + ni * 8 + (lane & 3) * 2 + h;
                atomicAdd(&bsum[col], cs[ni][h]);
                atomicAdd(&bsq[col], cq[ni][h]);
            }
        }
        __syncthreads();
        if (tid < 128) {
            int gc = bn + tid;
            atomicAdd(&g_bnsum[gc], bsum[tid]);
            atomicAdd(&g_bnsq[gc], bsq[tid]);
        }
    }
}

// ---------------- warp-per-node gather: one LDG.128/neighbor ----------------
__device__ __forceinline__ void acc_sm(float4& s, float4& m, uint4 u) {
    __half2 a = *(__half2*)&u.x, b = *(__half2*)&u.y;
    __half2 c = *(__half2*)&u.z, d = *(__half2*)&u.w;
    float2 f0 = __half22float2(a), f1 = __half22float2(b);
    float2 g0 = __half22float2(c), g1 = __half22float2(d);
    s.x += f0.x; s.y += f0.y; s.z += f1.x; s.w += f1.y;
    m.x = fmaxf(m.x, g0.x); m.y = fmaxf(m.y, g0.y);
    m.z = fmaxf(m.z, g1.x); m.w = fmaxf(m.w, g1.y);
}

__global__ void gather_reduce_kernel(int off, int cnt) {
    int gt = blockIdx.x * blockDim.x + threadIdx.x;
    int ln = gt >> 5;
    if (ln >= cnt) return;
    int node = off + ln;
    int lane = gt & 31;
    int start = g_rowstart[node];
    int deg = g_cnt[node];
    float4 s = make_float4(0.f, 0.f, 0.f, 0.f);
    float4 m = make_float4(-1e30f, -1e30f, -1e30f, -1e30f);
    int j = 0;
    for (; j + 4 <= deg; j += 4) {
        int nb0 = g_col[start + j],     nb1 = g_col[start + j + 1];
        int nb2 = g_col[start + j + 2], nb3 = g_col[start + j + 3];
        uint4 u0 = __ldg((const uint4*)(g_xxi + (size_t)nb0 * 256) + lane);
        uint4 u1 = __ldg((const uint4*)(g_xxi + (size_t)nb1 * 256) + lane);
        uint4 u2 = __ldg((const uint4*)(g_xxi + (size_t)nb2 * 256) + lane);
        uint4 u3 = __ldg((const uint4*)(g_xxi + (size_t)nb3 * 256) + lane);
        acc_sm(s, m, u0); acc_sm(s, m, u1); acc_sm(s, m, u2); acc_sm(s, m, u3);
    }
    for (; j < deg; j++) {
        int nb = g_col[start + j];
        uint4 u = __ldg((const uint4*)(g_xxi + (size_t)nb * 256) + lane);
        acc_sm(s, m, u);
    }
    if (deg == 0) m = make_float4(0.f, 0.f, 0.f, 0.f);
    f16_store4(g_cat + (size_t)node * 256 + lane * 4, s);
    f16_store4(g_am + (size_t)node * 128 + lane * 4, m);
}

// ---------------- GRU cell elementwise (fp16 in, fp16 out) ----------------
__device__ __forceinline__ float gru1(float ir, float hr, float iz, float hz,
                                      float inn, float hn, float xv) {
    float r = 1.f / (1.f + expf(-(ir + hr)));
    float z = 1.f / (1.f + expf(-(iz + hz)));
    float nc = tanhf(inn + r * hn);
    return (1.f - z) * nc + z * xv;
}
__device__ __forceinline__ float4 ld_h4(const __half* p) {
    uint2 u = *(const uint2*)p;
    float2 a = __half22float2(*(__half2*)&u.x);
    float2 b = __half22float2(*(__half2*)&u.y);
    return make_float4(a.x, a.y, b.x, b.y);
}

__global__ void gru_kernel(const float* __restrict__ x, int M) {
    int idx = blockIdx.x * blockDim.x + threadIdx.x;
    if (idx >= M * 32) return;
    int node = idx >> 5;
    int c = (idx & 31) * 4;
    const __half* gi = g_gi + (size_t)node * 384;
    const __half* gh = g_gh + (size_t)node * 384;
    float4 ir = ld_h4(gi + c);
    float4 iz = ld_h4(gi + 128 + c);
    float4 in = ld_h4(gi + 256 + c);
    float4 hr = ld_h4(gh + c);
    float4 hz = ld_h4(gh + 128 + c);
    float4 hn = ld_h4(gh + 256 + c);
    float4 xv = *(const float4*)(x + (size_t)node * 128 + c);
    float4 o;
    o.x = gru1(ir.x, hr.x, iz.x, hz.x, in.x, hn.x, xv.x);
    o.y = gru1(ir.y, hr.y, iz.y, hz.y, in.y, hn.y, xv.y);
    o.z = gru1(ir.z, hr.z, iz.z, hz.z, in.z, hn.z, xv.z);
    o.w = gru1(ir.w, hr.w, iz.w, hz.w, in.w, hn.w, xv.w);
    f16_store4(g_cat + (size_t)node * 256 + 128 + c, o);
}

// ---------------- batchnorm normalize ----------------
__global__ void bn_norm_kernel(float* __restrict__ out, const float* __restrict__ gamma,
                               const float* __restrict__ beta, int M, float invM) {
    int idx = blockIdx.x * blockDim.x + threadIdx.x;
    if (idx >= M * 32) return;
    int node = idx >> 5;
    int c = (idx & 31) * 4;
    float4 v = *(float4*)(out + (size_t)node * 128 + c);
    float4 sm = *(const float4*)(g_bnsum + c);
    float4 sq = *(const float4*)(g_bnsq + c);
    float4 gm = *(const float4*)(gamma + c);
    float4 bt = *(const float4*)(beta + c);
    float4 o;
    { float mean = sm.x * invM, var = sq.x * invM - mean * mean;
      o.x = gm.x * (v.x - mean) * rsqrtf(var + 1e-5f) + bt.x; }
    { float mean = sm.y * invM, var = sq.y * invM - mean * mean;
      o.y = gm.y * (v.y - mean) * rsqrtf(var + 1e-5f) + bt.y; }
    { float mean = sm.z * invM, var = sq.z * invM - mean * mean;
      o.z = gm.z * (v.z - mean) * rsqrtf(var + 1e-5f) + bt.z; }
    { float mean = sm.w * invM, var = sq.w * invM - mean * mean;
      o.w = gm.w * (v.w - mean) * rsqrtf(var + 1e-5f) + bt.w; }
    *(float4*)(out + (size_t)node * 128 + c) = o;
}

// ---------------- launch ----------------
extern "C" void kernel_launch(void* const* d_in, const int* in_sizes, int n_in,
                              void* d_out, int out_size) {
    const float* x       = (const float*)d_in[0];
    const int*   edges   = (const int*)d_in[1];
    const float* W_aff   = (const float*)d_in[2];
    const float* b_aff   = (const float*)d_in[3];
    const float* W_ih    = (const float*)d_in[4];
    const float* b_ih    = (const float*)d_in[5];
    const float* W_hh    = (const float*)d_in[6];
    const float* b_hh    = (const float*)d_in[7];
    const float* W_merge = (const float*)d_in[8];
    const float* b_merge = (const float*)d_in[9];
    const float* eps     = (const float*)d_in[10];
    const float* W1      = (const float*)d_in[11];
    const float* b1      = (const float*)d_in[12];
    const float* W2      = (const float*)d_in[13];
    const float* b2      = (const float*)d_in[14];
    const float* gamma   = (const float*)d_in[15];
    const float* beta    = (const float*)d_in[16];
    float* out = (float*)d_out;

    int M = in_sizes[0] / 128;
    int E = in_sizes[1] / 2;

    __half *p_gh, *p_gi, *p_xxi, *p_xf, *p_am, *p_cat, *p_hf, *p_tf, *p_wfh, *p_wfl;
    cudaGetSymbolAddress((void**)&p_gh, g_gh);
    cudaGetSymbolAddress((void**)&p_gi, g_gi);
    cudaGetSymbolAddress((void**)&p_xxi, g_xxi);
    cudaGetSymbolAddress((void**)&p_xf, g_xf);
    cudaGetSymbolAddress((void**)&p_am, g_am);
    cudaGetSymbolAddress((void**)&p_cat, g_cat);
    cudaGetSymbolAddress((void**)&p_hf, g_hf);
    cudaGetSymbolAddress((void**)&p_tf, g_tf);
    cudaGetSymbolAddress((void**)&p_wfh, g_wf_h);
    cudaGetSymbolAddress((void**)&p_wfl, g_wf_l);

    cudaFuncSetAttribute(hmma_gemm_f16, cudaFuncAttributeMaxDynamicSharedMemorySize, GEMM2_SMEM_MAX);

    static cudaStream_t s1 = nullptr;
    static cudaEvent_t evR = nullptr, evCSR = nullptr, evXI = nullptr, evGH = nullptr;
    static cudaEvent_t evG0 = nullptr, evGI0 = nullptr;
    if (!s1) {
        cudaStreamCreateWithFlags(&s1, cudaStreamNonBlocking);
        cudaEventCreateWithFlags(&evR, cudaEventDisableTiming);
        cudaEventCreateWithFlags(&evCSR, cudaEventDisableTiming);
        cudaEventCreateWithFlags(&evXI, cudaEventDisableTiming);
        cudaEventCreateWithFlags(&evGH, cudaEventDisableTiming);
        cudaEventCreateWithFlags(&evG0, cudaEventDisableTiming);
        cudaEventCreateWithFlags(&evGI0, cudaEventDisableTiming);
    }
    cudaStream_t s0 = 0;

    const uint32_t ST1 = 32768, SM1 = 1024 + 2 * ST1;   // single-B
    const uint32_t ST2 = 49152, SM2 = 1024 + 2 * ST2;   // two-term

    int mb = (M + 127) / 128;
    int nb = (M + 1023) / 1024;

    // root: zero counters (CSR count + BN accumulators)
    zero_init_kernel<<<(M + 255) / 256, 256, 0, s0>>>(M);
    cudaEventRecord(evR, s0);

    // ---- branch s1: CSR build ----
    cudaStreamWaitEvent(s1, evR, 0);
    count_kernel<<<(E + 255) / 256, 256, 0, s1>>>(edges, E);
    scan1_kernel<<<nb, 1024, 0, s1>>>(M);
    scan2_kernel<<<1, 128, 0, s1>>>(nb);
    scan3_kernel<<<(M + 255) / 256, 256, 0, s1>>>(M);
    fill_kernel<<<(E + 255) / 256, 256, 0, s1>>>(edges, E);
    cudaEventRecord(evCSR, s1);

    // ---- main stream: splits + xi GEMM ----
    {
        int n4 = M * 128 / 4;
        split_kernel<<<(n4 + 255) / 256, 256, 0, s0>>>(x, n4);
        split_weights_kernel<<<(53248 + 255) / 256, 256, 0, s0>>>(
            W_aff, W_ih, W_hh, W_merge, W1, W2);
    }
    // xi = x @ W_aff^T + b_aff -> interleaved fp16 (single-B; feeds damped path)
    hmma_gemm_f16<<<dim3(1, mb), 256, SM1, s0>>>(
        p_xf, p_wfh + F16_AFF, nullptr, b_aff,
        nullptr, p_xxi, 1, M, 128, 128, 0, 0, ST1, nullptr, nullptr);
    cudaEventRecord(evXI, s0);

    // ---- branch s1: gh GEMM (single-B), concurrent with gather ----
    cudaStreamWaitEvent(s1, evXI, 0);
    hmma_gemm_f16<<<dim3(3, mb), 256, SM1, s1>>>(
        p_xf, p_wfh + F16_HH, nullptr, b_hh,
        nullptr, p_gh, 0, M, 384, 128, 0, 0, ST1, nullptr, nullptr);
    cudaEventRecord(evGH, s1);

    // ---- gather in two halves; gi(half0) overlaps gather(half1) ----
    int M2 = (M / 2 + 127) & ~127;          // 128-aligned first half
    if (M2 > M) M2 = M;
    int Mr = M - M2;
    int mb0 = (M2 + 127) / 128;
    int mb1 = (Mr + 127) / 128;

    cudaStreamWaitEvent(s0, evCSR, 0);
    gather_reduce_kernel<<<(M2 * 32 + 255) / 256, 256, 0, s0>>>(0, M2);
    cudaEventRecord(evG0, s0);
    if (Mr > 0)
        gather_reduce_kernel<<<(Mr * 32 + 255) / 256, 256, 0, s0>>>(M2, Mr);

    // gi half0 on s1 (needs gather half0 + gh already queued there)
    cudaStreamWaitEvent(s1, evG0, 0);
    hmma_gemm_f16<<<dim3(3, mb0), 256, SM1, s1>>>(
        p_am, p_wfh + F16_IH, nullptr, b_ih,
        nullptr, p_gi, 0, M2, 384, 128, 0, 0, ST1, nullptr, nullptr);
    cudaEventRecord(evGI0, s1);

    // gi half1 on s0 (after gather half1)
    if (Mr > 0)
        hmma_gemm_f16<<<dim3(3, mb1), 256, SM1, s0>>>(
            p_am + (size_t)M2 * 128, p_wfh + F16_IH, nullptr, b_ih,
            nullptr, p_gi + (size_t)M2 * 384, 0, Mr, 384, 128, 0, 0, ST1, nullptr, nullptr);

    // GRU (needs gi both halves + gh) -> cat[:, 128:)
    cudaStreamWaitEvent(s0, evGI0, 0);
    cudaStreamWaitEvent(s0, evGH, 0);
    gru_kernel<<<(M * 32 + 255) / 256, 256, 0, s0>>>(x, M);

    // h = cat @ W_merge^T + b_merge + eps*x (2-term, fp16 out)
    hmma_gemm_f16<<<dim3(1, mb), 256, SM2, s0>>>(
        p_cat, p_wfh + F16_MG, p_wfl + F16_MG, b_merge,
        nullptr, p_hf, 0, M, 128, 256, 0, 0, ST2, x, eps);

    // t = relu(h @ W1^T + b1) (2-term, fp16 out)
    hmma_gemm_f16<<<dim3(2, mb), 256, SM2, s0>>>(
        p_hf, p_wfh + F16_W1, p_wfl + F16_W1, b1,
        nullptr, p_tf, 0, M, 256, 128, 1, 0, ST2, nullptr, nullptr);

    // out = relu(t @ W2^T + b2) (fp32 -> d_out) + fused BN reduce (2-term)
    hmma_gemm_f16<<<dim3(1, mb), 256, SM2, s0>>>(
        p_tf, p_wfh + F16_W2, p_wfl + F16_W2, b2,
        out, nullptr, 0, M, 128, 256, 1, 1, ST2, nullptr, nullptr);

    // batchnorm normalize (train mode, biased variance)
    bn_norm_kernel<<<(M * 32 + 255) / 256, 256, 0, s0>>>(out, gamma, beta, M, 1.0f / (float)M);
}

// round 12
// speedup vs baseline: 1.3053x; 1.3053x over previous
#include <cuda_runtime.h>
#include <cuda_bf16.h>
#include <cuda_fp16.h>
#include <math.h>
#include <stdint.h>

// ---------------- problem-size constants ----------------
#define NMAX 100000
#define EMAX 1600000

// ---------------- device scratch ----------------
__device__ __align__(16) __half g_gh[(size_t)NMAX * 384];   // fp16: x @ W_hh^T + b_hh
__device__ __align__(16) __half g_gi[(size_t)NMAX * 384];   // fp16: agg_max @ W_ih^T + b_ih
__device__ __align__(16) __half g_xxi[(size_t)NMAX * 256];  // interleaved fp16 [x4|xi4] (gather)
__device__ __align__(16) __half g_xf[(size_t)NMAX * 128];   // plain fp16 x (gh A-side)
__device__ __align__(16) __half g_am[(size_t)NMAX * 128];   // fp16 agg_max (exact)
__device__ __align__(16) __half g_cat[(size_t)NMAX * 256];  // fp16 [agg_sum | rnn_out]
__device__ __align__(16) __half g_hf[(size_t)NMAX * 128];   // fp16 merge out
__device__ __align__(16) __half g_tf[(size_t)NMAX * 256];   // fp16 relu(W1...)

__device__ __align__(16) __nv_bfloat16 g_x_h[(size_t)NMAX * 128];   // bf16 pair x (xi GEMM)
__device__ __align__(16) __nv_bfloat16 g_x_l[(size_t)NMAX * 128];
__device__ __align__(16) __nv_bfloat16 g_wb_h[16384];   // W_aff bf16 pair
__device__ __align__(16) __nv_bfloat16 g_wb_l[16384];
__device__ __align__(16) __half g_wf_h[196608];         // fp16 weight pairs (ih,hh,mg,w1,w2)
__device__ __align__(16) __half g_wf_l[196608];

__device__ int g_cnt[NMAX];
__device__ int g_rowstart[NMAX];
__device__ int g_cursor[NMAX];
__device__ int g_col[EMAX];
__device__ int g_bsum[256];
__device__ int g_boff[256];
__device__ float g_bnsum[128];
__device__ float g_bnsq[128];

// fp16 weight offsets (elements)
#define F16_IH 0
#define F16_HH 49152
#define F16_MG 98304
#define F16_W1 131072
#define F16_W2 163840

// ---------------- low-level helpers (plain sm_80-class PTX) ----------------
__device__ __forceinline__ uint32_t smem_u32(const void* p) {
    uint32_t a;
    asm("{ .reg .u64 t; cvta.to.shared.u64 t, %1; cvt.u32.u64 %0, t; }" : "=r"(a) : "l"(p));
    return a;
}
__device__ __forceinline__ void cpasync16(uint32_t dst, const void* src) {
    asm volatile("cp.async.cg.shared.global [%0], [%1], 16;" :: "r"(dst), "l"(src));
}
__device__ __forceinline__ void cp_commit() {
    asm volatile("cp.async.commit_group;" ::: "memory");
}
__device__ __forceinline__ void cp_wait1() {
    asm volatile("cp.async.wait_group 1;" ::: "memory");
}
__device__ __forceinline__ void cp_wait0() {
    asm volatile("cp.async.wait_group 0;" ::: "memory");
}
__device__ __forceinline__ void ldsm4(uint32_t* r, uint32_t addr) {
    asm volatile("ldmatrix.sync.aligned.m8n8.x4.shared.b16 {%0,%1,%2,%3}, [%4];"
                 : "=r"(r[0]), "=r"(r[1]), "=r"(r[2]), "=r"(r[3]) : "r"(addr));
}
__device__ __forceinline__ void mma_bf16(float* d, const uint32_t* a, const uint32_t* b) {
    asm volatile(
        "mma.sync.aligned.m16n8k16.row.col.f32.bf16.bf16.f32 "
        "{%0,%1,%2,%3}, {%4,%5,%6,%7}, {%8,%9}, {%0,%1,%2,%3};"
        : "+f"(d[0]), "+f"(d[1]), "+f"(d[2]), "+f"(d[3])
        : "r"(a[0]), "r"(a[1]), "r"(a[2]), "r"(a[3]), "r"(b[0]), "r"(b[1]));
}
__device__ __forceinline__ void mma_f16(float* d, const uint32_t* a, const uint32_t* b) {
    asm volatile(
        "mma.sync.aligned.m16n8k16.row.col.f32.f16.f16.f32 "
        "{%0,%1,%2,%3}, {%4,%5,%6,%7}, {%8,%9}, {%0,%1,%2,%3};"
        : "+f"(d[0]), "+f"(d[1]), "+f"(d[2]), "+f"(d[3])
        : "r"(a[0]), "r"(a[1]), "r"(a[2]), "r"(a[3]), "r"(b[0]), "r"(b[1]));
}

// ---------------- split helpers ----------------
__device__ __forceinline__ void split1(float v, unsigned short& hb, unsigned short& lb) {
    __nv_bfloat16 h = __float2bfloat16(v);
    float hf = __bfloat162float(h);
    __nv_bfloat16 l = __float2bfloat16(v - hf);
    hb = __bfloat16_as_ushort(h);
    lb = __bfloat16_as_ushort(l);
}
__device__ __forceinline__ void split_store4(__nv_bfloat16* ph, __nv_bfloat16* pl, float4 v) {
    unsigned short h0, h1, h2, h3, l0, l1, l2, l3;
    split1(v.x, h0, l0); split1(v.y, h1, l1); split1(v.z, h2, l2); split1(v.w, h3, l3);
    *(uint2*)ph = make_uint2((uint32_t)h0 | ((uint32_t)h1 << 16), (uint32_t)h2 | ((uint32_t)h3 << 16));
    *(uint2*)pl = make_uint2((uint32_t)l0 | ((uint32_t)l1 << 16), (uint32_t)l2 | ((uint32_t)l3 << 16));
}
__device__ __forceinline__ void f16_split1(float v, unsigned short& hb, unsigned short& lb) {
    __half h = __float2half_rn(v);
    float hf = __half2float(h);
    __half l = __float2half_rn(v - hf);
    hb = __half_as_ushort(h);
    lb = __half_as_ushort(l);
}
__device__ __forceinline__ void f16_split_store4(__half* ph, __half* pl, float4 v) {
    unsigned short h0, h1, h2, h3, l0, l1, l2, l3;
    f16_split1(v.x, h0, l0); f16_split1(v.y, h1, l1);
    f16_split1(v.z, h2, l2); f16_split1(v.w, h3, l3);
    *(uint2*)ph = make_uint2((uint32_t)h0 | ((uint32_t)h1 << 16), (uint32_t)h2 | ((uint32_t)h3 << 16));
    *(uint2*)pl = make_uint2((uint32_t)l0 | ((uint32_t)l1 << 16), (uint32_t)l2 | ((uint32_t)l3 << 16));
}
__device__ __forceinline__ void f16_store4(__half* p, float4 v) {
    __half2 a = __floats2half2_rn(v.x, v.y);
    __half2 b = __floats2half2_rn(v.z, v.w);
    *(uint2*)p = make_uint2(*(uint32_t*)&a, *(uint32_t*)&b);
}

// x: bf16 pair (xi GEMM) + interleaved fp16 x-slots of xxi + plain fp16 copy
__global__ void split_kernel(const float* __restrict__ in, int n4) {
    int i = blockIdx.x * blockDim.x + threadIdx.x;
    if (i >= n4) return;
    float4 v = ((const float4*)in)[i];
    split_store4(g_x_h + (size_t)i * 4, g_x_l + (size_t)i * 4, v);
    f16_store4(g_xf + (size_t)i * 4, v);
    int node = i >> 5;
    int c4 = i & 31;
    __half2 f0 = __floats2half2_rn(v.x, v.y);
    __half2 f1 = __floats2half2_rn(v.z, v.w);
    *(uint2*)(g_xxi + (size_t)node * 256 + c4 * 8) = make_uint2(*(uint32_t*)&f0, *(uint32_t*)&f1);
}

// Weights. float4 idx i in [0,53248): aff [0,4096) -> bf16 pair; rest -> fp16 pair
// j=i-4096: ih [0,12288) hh [12288,24576) mg [24576,32768) w1 [32768,40960) w2 [40960,49152)
__global__ void split_weights_kernel(const float* __restrict__ Waff, const float* __restrict__ Wih,
                                     const float* __restrict__ Whh, const float* __restrict__ Wmg,
                                     const float* __restrict__ W1, const float* __restrict__ W2) {
    int i = blockIdx.x * blockDim.x + threadIdx.x;
    if (i >= 53248) return;
    if (i < 4096) {
        float4 v = ((const float4*)Waff)[i];
        split_store4(g_wb_h + (size_t)i * 4, g_wb_l + (size_t)i * 4, v);
        return;
    }
    int j = i - 4096;
    const float* src; int base;
    if (j < 12288)      { src = Wih; base = 0; }
    else if (j < 24576) { src = Whh; base = 12288; }
    else if (j < 32768) { src = Wmg; base = 24576; }
    else if (j < 40960) { src = W1;  base = 32768; }
    else                { src = W2;  base = 40960; }
    float4 v = ((const float4*)src)[j - base];
    f16_split_store4(g_wf_h + (size_t)j * 4, g_wf_l + (size_t)j * 4, v);
}

// ---------------- init ----------------
__global__ void zero_init_kernel(int n) {
    int i = blockIdx.x * blockDim.x + threadIdx.x;
    if (i < n) g_cnt[i] = 0;
    if (i < 128) { g_bnsum[i] = 0.f; g_bnsq[i] = 0.f; }
}

// ---------------- CSR build ----------------
__global__ void count_kernel(const int* __restrict__ edges, int E) {
    int e = blockIdx.x * blockDim.x + threadIdx.x;
    if (e >= E) return;
    atomicAdd(&g_cnt[edges[E + e]], 1);
}
__global__ void scan1_kernel(int n) {
    __shared__ int sh[1024];
    int tid = threadIdx.x;
    int i = blockIdx.x * 1024 + tid;
    int v = (i < n) ? g_cnt[i] : 0;
    sh[tid] = v;
    __syncthreads();
    for (int off = 1; off < 1024; off <<= 1) {
        int t = (tid >= off) ? sh[tid - off] : 0;
        __syncthreads();
        sh[tid] += t;
        __syncthreads();
    }
    if (i < n) g_rowstart[i] = sh[tid] - v;
    if (tid == 1023) g_bsum[blockIdx.x] = sh[1023];
}
__global__ void scan2_kernel(int nb) {
    __shared__ int sh[128];
    int t = threadIdx.x;
    int v = (t < nb) ? g_bsum[t] : 0;
    sh[t] = v;
    __syncthreads();
    for (int off = 1; off < 128; off <<= 1) {
        int u = (t >= off) ? sh[t - off] : 0;
        __syncthreads();
        sh[t] += u;
        __syncthreads();
    }
    if (t < nb) g_boff[t] = sh[t] - v;
}
__global__ void scan3_kernel(int n) {
    int i = blockIdx.x * blockDim.x + threadIdx.x;
    if (i < n) {
        int v = g_rowstart[i] + g_boff[i >> 10];
        g_rowstart[i] = v;
        g_cursor[i] = v;
    }
}
__global__ void fill_kernel(const int* __restrict__ edges, int E) {
    int e = blockIdx.x * blockDim.x + threadIdx.x;
    if (e >= E) return;
    int src = edges[e];
    int dst = edges[E + e];
    int pos = atomicAdd(&g_cursor[dst], 1);
    g_col[pos] = src;
}

__device__ __forceinline__ uint32_t sw128(uint32_t r, uint32_t u) {
    return r * 128u + ((u ^ (r & 7u)) << 4);
}

// ---------------- bf16 3-term GEMM (xi only): out -> interleaved fp16 xxi ----------------
#define STAGE3_BYTES 65536
#define GEMM3_SMEM (1024 + 2 * STAGE3_BYTES)

__global__ __launch_bounds__(256, 1)
void hmma_gemm_bf16(const __nv_bfloat16* __restrict__ Ah, const __nv_bfloat16* __restrict__ Al,
                    const __nv_bfloat16* __restrict__ Bh, const __nv_bfloat16* __restrict__ Bl,
                    const float* __restrict__ bias, __half* __restrict__ Cil,
                    int M, int Ntot, int K)
{
    extern __shared__ char dsm[];
    uint32_t sb0 = smem_u32(dsm);
    uint32_t base0 = (sb0 + 1023u) & ~1023u;

    int tid = threadIdx.x;
    int lane = tid & 31;
    int wid = tid >> 5;
    int wm = wid >> 2;
    int wn = wid & 3;
    int bm = blockIdx.y * 128, bn = blockIdx.x * 128;

    float acc[4][4][4];
#pragma unroll
    for (int i = 0; i < 4; i++)
#pragma unroll
        for (int j = 0; j < 4; j++)
#pragma unroll
            for (int k = 0; k < 4; k++) acc[i][j][k] = 0.f;

    const int NSt = K >> 6;
    const __nv_bfloat16* srcs[4] = { Ah, Al, Bh, Bl };
    const int rbase[4] = { bm, bm, bn, bn };
    const int rmax[4]  = { M - 1, M - 1, Ntot - 1, Ntot - 1 };

    auto load_stage = [&](int s) {
        uint32_t buf = base0 + (uint32_t)(s & 1) * STAGE3_BYTES;
        int kc = s * 64;
#pragma unroll
        for (int t = 0; t < 4; t++) {
            const __nv_bfloat16* src = srcs[t];
            int rb = rbase[t], rm = rmax[t];
            uint32_t dbase = buf + t * 16384u;
#pragma unroll
            for (int i = 0; i < 4; i++) {
                int idx = tid + i * 256;
                uint32_t r = (uint32_t)(idx >> 3);
                uint32_t u = (uint32_t)(idx & 7);
                int gr = rb + (int)r; if (gr > rm) gr = rm;
                cpasync16(dbase + sw128(r, u), src + (size_t)gr * K + kc + u * 8);
            }
        }
        cp_commit();
    };

    load_stage(0);
    for (int s = 0; s < NSt; s++) {
        if (s + 1 < NSt) { load_stage(s + 1); cp_wait1(); }
        else cp_wait0();
        __syncthreads();
        uint32_t buf = base0 + (uint32_t)(s & 1) * STAGE3_BYTES;
#pragma unroll
        for (int ks = 0; ks < 4; ks++) {
            uint32_t bh[4][2], bl[4][2];
#pragma unroll
            for (int jp = 0; jp < 2; jp++) {
                uint32_t r = (uint32_t)(wn * 32 + jp * 16) + (uint32_t)(lane & 7) + (uint32_t)((lane >> 4) << 3);
                uint32_t u = (uint32_t)(ks * 2 + ((lane >> 3) & 1));
                uint32_t off = sw128(r, u);
                uint32_t t4[4];
                ldsm4(t4, buf + 32768u + off);
                bh[jp * 2][0] = t4[0]; bh[jp * 2][1] = t4[1];
                bh[jp * 2 + 1][0] = t4[2]; bh[jp * 2 + 1][1] = t4[3];
                ldsm4(t4, buf + 49152u + off);
                bl[jp * 2][0] = t4[0]; bl[jp * 2][1] = t4[1];
                bl[jp * 2 + 1][0] = t4[2]; bl[jp * 2 + 1][1] = t4[3];
            }
#pragma unroll
            for (int mi = 0; mi < 4; mi++) {
                uint32_t r = (uint32_t)(wm * 64 + mi * 16) + (uint32_t)(lane & 15);
                uint32_t u = (uint32_t)(ks * 2 + (lane >> 4));
                uint32_t off = sw128(r, u);
                uint32_t ahf[4], alf[4];
                ldsm4(ahf, buf + off);
                ldsm4(alf, buf + 16384u + off);
#pragma unroll
                for (int ni = 0; ni < 4; ni++) {
                    mma_bf16(acc[mi][ni], ahf, bh[ni]);
                    mma_bf16(acc[mi][ni], ahf, bl[ni]);
                    mma_bf16(acc[mi][ni], alf, bh[ni]);
                }
            }
        }
        __syncthreads();
    }

#pragma unroll
    for (int mi = 0; mi < 4; mi++) {
#pragma unroll
        for (int rr = 0; rr < 2; rr++) {
            int gr = bm + wm * 64 + mi * 16 + (lane >> 2) + rr * 8;
            if (gr >= M) continue;
#pragma unroll
            for (int ni = 0; ni < 4; ni++) {
                int gc = bn + wn * 32 + ni * 8 + (lane & 3) * 2;
                float v0 = acc[mi][ni][rr * 2 + 0];
                float v1 = acc[mi][ni][rr * 2 + 1];
                float2 bv = *(const float2*)(bias + gc);
                v0 += bv.x; v1 += bv.y;
                __half2 hv = __floats2half2_rn(v0, v1);
                // interleaved xxi: xi pair at node*256 + (gc>>2)*8 + 4 + (gc&3)
                *(uint32_t*)(Cil + (size_t)gr * 256 + ((gc >> 2) << 3) + 4 + (gc & 3)) = *(uint32_t*)&hv;
            }
        }
    }
}

// ---------------- fp16 GEMM: D = A_f16 @ (Bh[+Bl])^T + bias ----------------
// Bl==nullptr -> single-B (1 MMA/step). Stage layout fixed (48KB) in both modes.
#define STAGE2_BYTES 49152
#define GEMM2_SMEM (1024 + 2 * STAGE2_BYTES)

__global__ __launch_bounds__(256, 2)
void hmma_gemm_f16(const __half* __restrict__ A,
                   const __half* __restrict__ Bh, const __half* __restrict__ Bl,
                   const float* __restrict__ bias,
                   float* __restrict__ Cf, __half* __restrict__ Cf16,
                   int M, int Ntot, int K, int relu, int bnred,
                   const float* __restrict__ resid, const float* __restrict__ eps_ptr)
{
    extern __shared__ char dsm[];
    uint32_t sb0 = smem_u32(dsm);
    uint32_t base0 = (sb0 + 1023u) & ~1023u;
    char* p0 = dsm + (base0 - sb0);

    int tid = threadIdx.x;
    int lane = tid & 31;
    int wid = tid >> 5;
    int wm = wid >> 2;
    int wn = wid & 3;
    int bm = blockIdx.y * 128, bn = blockIdx.x * 128;

    float acc[4][4][4];
#pragma unroll
    for (int i = 0; i < 4; i++)
#pragma unroll
        for (int j = 0; j < 4; j++)
#pragma unroll
            for (int k = 0; k < 4; k++) acc[i][j][k] = 0.f;

    const int NSt = K >> 6;

    auto load_stage = [&](int s) {
        uint32_t buf = base0 + (uint32_t)(s & 1) * STAGE2_BYTES;
        int kc = s * 64;
        // A tile: 128 rows x 8 units
#pragma unroll
        for (int i = 0; i < 4; i++) {
            int idx = tid + i * 256;
            uint32_t r = (uint32_t)(idx >> 3);
            uint32_t u = (uint32_t)(idx & 7);
            int gr = bm + (int)r; if (gr > M - 1) gr = M - 1;
            cpasync16(buf + sw128(r, u), A + (size_t)gr * K + kc + u * 8);
        }
        // Bh tile
#pragma unroll
        for (int i = 0; i < 4; i++) {
            int idx = tid + i * 256;
            uint32_t r = (uint32_t)(idx >> 3);
            uint32_t u = (uint32_t)(idx & 7);
            int gr = bn + (int)r; if (gr > Ntot - 1) gr = Ntot - 1;
            cpasync16(buf + 16384u + sw128(r, u), Bh + (size_t)gr * K + kc + u * 8);
        }
        // Bl tile (optional)
        if (Bl) {
#pragma unroll
            for (int i = 0; i < 4; i++) {
                int idx = tid + i * 256;
                uint32_t r = (uint32_t)(idx >> 3);
                uint32_t u = (uint32_t)(idx & 7);
                int gr = bn + (int)r; if (gr > Ntot - 1) gr = Ntot - 1;
                cpasync16(buf + 32768u + sw128(r, u), Bl + (size_t)gr * K + kc + u * 8);
            }
        }
        cp_commit();
    };

    load_stage(0);
    for (int s = 0; s < NSt; s++) {
        if (s + 1 < NSt) { load_stage(s + 1); cp_wait1(); }
        else cp_wait0();
        __syncthreads();
        uint32_t buf = base0 + (uint32_t)(s & 1) * STAGE2_BYTES;
#pragma unroll
        for (int ks = 0; ks < 4; ks++) {
            uint32_t bh[4][2], bl[4][2];
#pragma unroll
            for (int jp = 0; jp < 2; jp++) {
                uint32_t r = (uint32_t)(wn * 32 + jp * 16) + (uint32_t)(lane & 7) + (uint32_t)((lane >> 4) << 3);
                uint32_t u = (uint32_t)(ks * 2 + ((lane >> 3) & 1));
                uint32_t off = sw128(r, u);
                uint32_t t4[4];
                ldsm4(t4, buf + 16384u + off);
                bh[jp * 2][0] = t4[0]; bh[jp * 2][1] = t4[1];
                bh[jp * 2 + 1][0] = t4[2]; bh[jp * 2 + 1][1] = t4[3];
                if (Bl) {
                    ldsm4(t4, buf + 32768u + off);
                    bl[jp * 2][0] = t4[0]; bl[jp * 2][1] = t4[1];
                    bl[jp * 2 + 1][0] = t4[2]; bl[jp * 2 + 1][1] = t4[3];
                }
            }
#pragma unroll
            for (int mi = 0; mi < 4; mi++) {
                uint32_t r = (uint32_t)(wm * 64 + mi * 16) + (uint32_t)(lane & 15);
                uint32_t u = (uint32_t)(ks * 2 + (lane >> 4));
                uint32_t off = sw128(r, u);
                uint32_t af[4];
                ldsm4(af, buf + off);
#pragma unroll
                for (int ni = 0; ni < 4; ni++) {
                    mma_f16(acc[mi][ni], af, bh[ni]);
                    if (Bl) mma_f16(acc[mi][ni], af, bl[ni]);
                }
            }
        }
        __syncthreads();
    }

    // ---------------- epilogue ----------------
    float e = resid ? __ldg(eps_ptr) : 0.f;
    float cs[4][2], cq[4][2];
#pragma unroll
    for (int ni = 0; ni < 4; ni++) { cs[ni][0] = cs[ni][1] = cq[ni][0] = cq[ni][1] = 0.f; }

#pragma unroll
    for (int mi = 0; mi < 4; mi++) {
#pragma unroll
        for (int rr = 0; rr < 2; rr++) {
            int gr = bm + wm * 64 + mi * 16 + (lane >> 2) + rr * 8;
            if (gr >= M) continue;
#pragma unroll
            for (int ni = 0; ni < 4; ni++) {
                int gc = bn + wn * 32 + ni * 8 + (lane & 3) * 2;
                float v0 = acc[mi][ni][rr * 2 + 0];
                float v1 = acc[mi][ni][rr * 2 + 1];
                float2 bv = *(const float2*)(bias + gc);
                v0 += bv.x; v1 += bv.y;
                if (resid) {
                    float2 rv = *(const float2*)(resid + (size_t)gr * Ntot + gc);
                    v0 += e * rv.x; v1 += e * rv.y;
                }
                if (relu) { v0 = fmaxf(v0, 0.f); v1 = fmaxf(v1, 0.f); }
                if (bnred) {
                    cs[ni][0] += v0; cq[ni][0] += v0 * v0;
                    cs[ni][1] += v1; cq[ni][1] += v1 * v1;
                }
                if (Cf) {
                    *(float2*)(Cf + (size_t)gr * Ntot + gc) = make_float2(v0, v1);
                } else {
                    __half2 hv = __floats2half2_rn(v0, v1);
                    *(uint32_t*)(Cf16 + (size_t)gr * Ntot + gc) = *(uint32_t*)&hv;
                }
            }
        }
    }

    if (bnred) {
        float* bsum = (float*)p0;
        float* bsq  = bsum + 128;
        __syncthreads();
        if (tid < 256) ((float*)p0)[tid] = 0.f;
        __syncthreads();
#pragma unroll
        for (int ni = 0; ni < 4; ni++) {
#pragma unroll
            for (int h = 0; h < 2; h++) {
                int col = wn * 32 + ni * 8 + (lane & 3) * 2 + h;
                atomicAdd(&bsum[col], cs[ni][h]);
                atomicAdd(&bsq[col], cq[ni][h]);
            }
        }
        __syncthreads();
        if (tid < 128) {
            int gc = bn + tid;
            atomicAdd(&g_bnsum[gc], bsum[tid]);
            atomicAdd(&g_bnsq[gc], bsq[tid]);
        }
    }
}

// ---------------- warp-per-node gather: one LDG.128/neighbor ----------------
__device__ __forceinline__ void acc_sm(float4& s, float4& m, uint4 u) {
    __half2 a = *(__half2*)&u.x, b = *(__half2*)&u.y;
    __half2 c = *(__half2*)&u.z, d = *(__half2*)&u.w;
    float2 f0 = __half22float2(a), f1 = __half22float2(b);
    float2 g0 = __half22float2(c), g1 = __half22float2(d);
    s.x += f0.x; s.y += f0.y; s.z += f1.x; s.w += f1.y;
    m.x = fmaxf(m.x, g0.x); m.y = fmaxf(m.y, g0.y);
    m.z = fmaxf(m.z, g1.x); m.w = fmaxf(m.w, g1.y);
}

__global__ void gather_reduce_kernel(int n) {
    int gt = blockIdx.x * blockDim.x + threadIdx.x;
    int node = gt >> 5;
    if (node >= n) return;
    int lane = gt & 31;
    int start = g_rowstart[node];
    int deg = g_cnt[node];
    float4 s = make_float4(0.f, 0.f, 0.f, 0.f);
    float4 m = make_float4(-1e30f, -1e30f, -1e30f, -1e30f);
    int j = 0;
    for (; j + 4 <= deg; j += 4) {
        int nb0 = g_col[start + j],     nb1 = g_col[start + j + 1];
        int nb2 = g_col[start + j + 2], nb3 = g_col[start + j + 3];
        uint4 u0 = __ldg((const uint4*)(g_xxi + (size_t)nb0 * 256) + lane);
        uint4 u1 = __ldg((const uint4*)(g_xxi + (size_t)nb1 * 256) + lane);
        uint4 u2 = __ldg((const uint4*)(g_xxi + (size_t)nb2 * 256) + lane);
        uint4 u3 = __ldg((const uint4*)(g_xxi + (size_t)nb3 * 256) + lane);
        acc_sm(s, m, u0); acc_sm(s, m, u1); acc_sm(s, m, u2); acc_sm(s, m, u3);
    }
    for (; j < deg; j++) {
        int nb = g_col[start + j];
        uint4 u = __ldg((const uint4*)(g_xxi + (size_t)nb * 256) + lane);
        acc_sm(s, m, u);
    }
    if (deg == 0) m = make_float4(0.f, 0.f, 0.f, 0.f);
    // agg_sum -> cat[:,0:128) fp16; agg_max -> am fp16 (exact: max of fp16 values)
    f16_store4(g_cat + (size_t)node * 256 + lane * 4, s);
    f16_store4(g_am + (size_t)node * 128 + lane * 4, m);
}

// ---------------- GRU cell elementwise (fp16 in, fp16 out) ----------------
__device__ __forceinline__ float gru1(float ir, float hr, float iz, float hz,
                                      float inn, float hn, float xv) {
    float r = 1.f / (1.f + expf(-(ir + hr)));
    float z = 1.f / (1.f + expf(-(iz + hz)));
    float nc = tanhf(inn + r * hn);
    return (1.f - z) * nc + z * xv;
}
__device__ __forceinline__ float4 ld_h4(const __half* p) {
    uint2 u = *(const uint2*)p;
    float2 a = __half22float2(*(__half2*)&u.x);
    float2 b = __half22float2(*(__half2*)&u.y);
    return make_float4(a.x, a.y, b.x, b.y);
}

__global__ void gru_kernel(const float* __restrict__ x, int M) {
    int idx = blockIdx.x * blockDim.x + threadIdx.x;
    if (idx >= M * 32) return;
    int node = idx >> 5;
    int c = (idx & 31) * 4;
    const __half* gi = g_gi + (size_t)node * 384;
    const __half* gh = g_gh + (size_t)node * 384;
    float4 ir = ld_h4(gi + c);
    float4 iz = ld_h4(gi + 128 + c);
    float4 in = ld_h4(gi + 256 + c);
    float4 hr = ld_h4(gh + c);
    float4 hz = ld_h4(gh + 128 + c);
    float4 hn = ld_h4(gh + 256 + c);
    float4 xv = *(const float4*)(x + (size_t)node * 128 + c);
    float4 o;
    o.x = gru1(ir.x, hr.x, iz.x, hz.x, in.x, hn.x, xv.x);
    o.y = gru1(ir.y, hr.y, iz.y, hz.y, in.y, hn.y, xv.y);
    o.z = gru1(ir.z, hr.z, iz.z, hz.z, in.z, hn.z, xv.z);
    o.w = gru1(ir.w, hr.w, iz.w, hz.w, in.w, hn.w, xv.w);
    f16_store4(g_cat + (size_t)node * 256 + 128 + c, o);
}

// ---------------- batchnorm normalize ----------------
__global__ void bn_norm_kernel(float* __restrict__ out, const float* __restrict__ gamma,
                               const float* __restrict__ beta, int M, float invM) {
    int idx = blockIdx.x * blockDim.x + threadIdx.x;
    if (idx >= M * 32) return;
    int node = idx >> 5;
    int c = (idx & 31) * 4;
    float4 v = *(float4*)(out + (size_t)node * 128 + c);
    float4 sm = *(const float4*)(g_bnsum + c);
    float4 sq = *(const float4*)(g_bnsq + c);
    float4 gm = *(const float4*)(gamma + c);
    float4 bt = *(const float4*)(beta + c);
    float4 o;
    { float mean = sm.x * invM, var = sq.x * invM - mean * mean;
      o.x = gm.x * (v.x - mean) * rsqrtf(var + 1e-5f) + bt.x; }
    { float mean = sm.y * invM, var = sq.y * invM - mean * mean;
      o.y = gm.y * (v.y - mean) * rsqrtf(var + 1e-5f) + bt.y; }
    { float mean = sm.z * invM, var = sq.z * invM - mean * mean;
      o.z = gm.z * (v.z - mean) * rsqrtf(var + 1e-5f) + bt.z; }
    { float mean = sm.w * invM, var = sq.w * invM - mean * mean;
      o.w = gm.w * (v.w - mean) * rsqrtf(var + 1e-5f) + bt.w; }
    *(float4*)(out + (size_t)node * 128 + c) = o;
}

// ---------------- launch ----------------
extern "C" void kernel_launch(void* const* d_in, const int* in_sizes, int n_in,
                              void* d_out, int out_size) {
    const float* x       = (const float*)d_in[0];
    const int*   edges   = (const int*)d_in[1];
    const float* W_aff   = (const float*)d_in[2];
    const float* b_aff   = (const float*)d_in[3];
    const float* W_ih    = (const float*)d_in[4];
    const float* b_ih    = (const float*)d_in[5];
    const float* W_hh    = (const float*)d_in[6];
    const float* b_hh    = (const float*)d_in[7];
    const float* W_merge = (const float*)d_in[8];
    const float* b_merge = (const float*)d_in[9];
    const float* eps     = (const float*)d_in[10];
    const float* W1      = (const float*)d_in[11];
    const float* b1      = (const float*)d_in[12];
    const float* W2      = (const float*)d_in[13];
    const float* b2      = (const float*)d_in[14];
    const float* gamma   = (const float*)d_in[15];
    const float* beta    = (const float*)d_in[16];
    float* out = (float*)d_out;

    int M = in_sizes[0] / 128;
    int E = in_sizes[1] / 2;

    __half *p_gh, *p_gi, *p_xxi, *p_xf, *p_am, *p_cat, *p_hf, *p_tf, *p_wfh, *p_wfl;
    __nv_bfloat16 *p_xh, *p_xl, *p_wbh, *p_wbl;
    cudaGetSymbolAddress((void**)&p_gh, g_gh);
    cudaGetSymbolAddress((void**)&p_gi, g_gi);
    cudaGetSymbolAddress((void**)&p_xxi, g_xxi);
    cudaGetSymbolAddress((void**)&p_xf, g_xf);
    cudaGetSymbolAddress((void**)&p_am, g_am);
    cudaGetSymbolAddress((void**)&p_cat, g_cat);
    cudaGetSymbolAddress((void**)&p_hf, g_hf);
    cudaGetSymbolAddress((void**)&p_tf, g_tf);
    cudaGetSymbolAddress((void**)&p_wfh, g_wf_h);
    cudaGetSymbolAddress((void**)&p_wfl, g_wf_l);
    cudaGetSymbolAddress((void**)&p_xh, g_x_h);
    cudaGetSymbolAddress((void**)&p_xl, g_x_l);
    cudaGetSymbolAddress((void**)&p_wbh, g_wb_h);
    cudaGetSymbolAddress((void**)&p_wbl, g_wb_l);

    cudaFuncSetAttribute(hmma_gemm_bf16, cudaFuncAttributeMaxDynamicSharedMemorySize, GEMM3_SMEM);
    cudaFuncSetAttribute(hmma_gemm_f16, cudaFuncAttributeMaxDynamicSharedMemorySize, GEMM2_SMEM);

    static cudaStream_t s1 = nullptr;
    static cudaEvent_t evR = nullptr, evCSR = nullptr, evXI = nullptr, evGH = nullptr;
    if (!s1) {
        cudaStreamCreateWithFlags(&s1, cudaStreamNonBlocking);
        cudaEventCreateWithFlags(&evR, cudaEventDisableTiming);
        cudaEventCreateWithFlags(&evCSR, cudaEventDisableTiming);
        cudaEventCreateWithFlags(&evXI, cudaEventDisableTiming);
        cudaEventCreateWithFlags(&evGH, cudaEventDisableTiming);
    }
    cudaStream_t s0 = 0;

    int mb = (M + 127) / 128;
    int nb = (M + 1023) / 1024;

    // root: zero counters (CSR count + BN accumulators)
    zero_init_kernel<<<(M + 255) / 256, 256, 0, s0>>>(M);
    cudaEventRecord(evR, s0);

    // ---- branch s1: CSR build ----
    cudaStreamWaitEvent(s1, evR, 0);
    count_kernel<<<(E + 255) / 256, 256, 0, s1>>>(edges, E);
    scan1_kernel<<<nb, 1024, 0, s1>>>(M);
    scan2_kernel<<<1, 128, 0, s1>>>(nb);
    scan3_kernel<<<(M + 255) / 256, 256, 0, s1>>>(M);
    fill_kernel<<<(E + 255) / 256, 256, 0, s1>>>(edges, E);
    cudaEventRecord(evCSR, s1);

    // ---- main stream: splits + xi GEMM ----
    {
        int n4 = M * 128 / 4;
        split_kernel<<<(n4 + 255) / 256, 256, 0, s0>>>(x, n4);
        split_weights_kernel<<<(53248 + 255) / 256, 256, 0, s0>>>(
            W_aff, W_ih, W_hh, W_merge, W1, W2);
    }
    // xi = x @ W_aff^T + b_aff -> interleaved fp16 slots of xxi
    hmma_gemm_bf16<<<dim3(1, mb), 256, GEMM3_SMEM, s0>>>(
        p_xh, p_xl, p_wbh, p_wbl, b_aff, p_xxi, M, 128, 128);
    cudaEventRecord(evXI, s0);

    // ---- branch s1: gh GEMM (single-B fp16), concurrent with gather ----
    cudaStreamWaitEvent(s1, evXI, 0);
    hmma_gemm_f16<<<dim3(3, mb), 256, GEMM2_SMEM, s1>>>(
        p_xf, p_wfh + F16_HH, nullptr, b_hh,
        nullptr, p_gh, M, 384, 128, 0, 0, nullptr, nullptr);
    cudaEventRecord(evGH, s1);

    // ---- main stream: gather (needs CSR + xxi) ----
    cudaStreamWaitEvent(s0, evCSR, 0);
    gather_reduce_kernel<<<(M * 32 + 255) / 256, 256, 0, s0>>>(M);

    // gi = agg_max @ W_ih^T + b_ih (single-B fp16; A exact fp16)
    hmma_gemm_f16<<<dim3(3, mb), 256, GEMM2_SMEM, s0>>>(
        p_am, p_wfh + F16_IH, nullptr, b_ih,
        nullptr, p_gi, M, 384, 128, 0, 0, nullptr, nullptr);

    // GRU (needs gi + gh) -> cat[:, 128:)
    cudaStreamWaitEvent(s0, evGH, 0);
    gru_kernel<<<(M * 32 + 255) / 256, 256, 0, s0>>>(x, M);

    // h = cat @ W_merge^T + b_merge + eps*x (2-term, fp16 out)
    hmma_gemm_f16<<<dim3(1, mb), 256, GEMM2_SMEM, s0>>>(
        p_cat, p_wfh + F16_MG, p_wfl + F16_MG, b_merge,
        nullptr, p_hf, M, 128, 256, 0, 0, x, eps);

    // t = relu(h @ W1^T + b1) (2-term, fp16 out)
    hmma_gemm_f16<<<dim3(2, mb), 256, GEMM2_SMEM, s0>>>(
        p_hf, p_wfh + F16_W1, p_wfl + F16_W1, b1,
        nullptr, p_tf, M, 256, 128, 1, 0, nullptr, nullptr);

    // out = relu(t @ W2^T + b2) (fp32 -> d_out) + fused BN reduce (2-term)
    hmma_gemm_f16<<<dim3(1, mb), 256, GEMM2_SMEM, s0>>>(
        p_tf, p_wfh + F16_W2, p_wfl + F16_W2, b2,
        out, nullptr, M, 128, 256, 1, 1, nullptr, nullptr);

    // batchnorm normalize (train mode, biased variance)
    bn_norm_kernel<<<(M * 32 + 255) / 256, 256, 0, s0>>>(out, gamma, beta, M, 1.0f / (float)M);
}

// round 13
// speedup vs baseline: 1.3702x; 1.0497x over previous
#include <cuda_runtime.h>
#include <cuda_fp16.h>
#include <math.h>
#include <stdint.h>

// ---------------- problem-size constants ----------------
#define NMAX 100000
#define EMAX 1600000

// ---------------- device scratch ----------------
__device__ __align__(16) __half g_gh[(size_t)NMAX * 384];   // fp16: x @ W_hh^T + b_hh
__device__ __align__(16) __half g_gi[(size_t)NMAX * 384];   // fp16: agg_max @ W_ih^T + b_ih
__device__ __align__(16) __half g_xxi[(size_t)NMAX * 256];  // interleaved fp16 [x4|xi4] (gather)
__device__ __align__(16) __half g_xf[(size_t)NMAX * 128];   // plain fp16 x (xi/gh A-side)
__device__ __align__(16) __half g_am[(size_t)NMAX * 128];   // fp16 agg_max (exact)
__device__ __align__(16) __half g_cat[(size_t)NMAX * 256];  // fp16 [agg_sum | rnn_out]
__device__ __align__(16) __half g_hf[(size_t)NMAX * 128];   // fp16 merge out
__device__ __align__(16) __half g_tf[(size_t)NMAX * 256];   // fp16 relu(W1...)

__device__ __align__(16) __half g_wf_h[212992];  // fp16 weight hi (aff,ih,hh,mg,w1,w2)
__device__ __align__(16) __half g_wf_l[212992];  // fp16 weight lo

__device__ int g_cnt[NMAX];
__device__ int g_rowstart[NMAX];
__device__ int g_cursor[NMAX];
__device__ int g_col[EMAX];
__device__ int g_bsum[256];
__device__ int g_boff[256];
__device__ float g_bnsum[128];
__device__ float g_bnsq[128];

// fp16 weight offsets (elements)
#define F16_AFF 0
#define F16_IH  16384
#define F16_HH  65536
#define F16_MG  114688
#define F16_W1  147456
#define F16_W2  180224

// ---------------- low-level helpers (plain sm_80-class PTX) ----------------
__device__ __forceinline__ uint32_t smem_u32(const void* p) {
    uint32_t a;
    asm("{ .reg .u64 t; cvta.to.shared.u64 t, %1; cvt.u32.u64 %0, t; }" : "=r"(a) : "l"(p));
    return a;
}
__device__ __forceinline__ void cpasync16(uint32_t dst, const void* src) {
    asm volatile("cp.async.cg.shared.global [%0], [%1], 16;" :: "r"(dst), "l"(src));
}
__device__ __forceinline__ void cp_commit() {
    asm volatile("cp.async.commit_group;" ::: "memory");
}
__device__ __forceinline__ void cp_wait1() {
    asm volatile("cp.async.wait_group 1;" ::: "memory");
}
__device__ __forceinline__ void cp_wait0() {
    asm volatile("cp.async.wait_group 0;" ::: "memory");
}
__device__ __forceinline__ void ldsm4(uint32_t* r, uint32_t addr) {
    asm volatile("ldmatrix.sync.aligned.m8n8.x4.shared.b16 {%0,%1,%2,%3}, [%4];"
                 : "=r"(r[0]), "=r"(r[1]), "=r"(r[2]), "=r"(r[3]) : "r"(addr));
}
__device__ __forceinline__ void mma_f16(float* d, const uint32_t* a, const uint32_t* b) {
    asm volatile(
        "mma.sync.aligned.m16n8k16.row.col.f32.f16.f16.f32 "
        "{%0,%1,%2,%3}, {%4,%5,%6,%7}, {%8,%9}, {%0,%1,%2,%3};"
        : "+f"(d[0]), "+f"(d[1]), "+f"(d[2]), "+f"(d[3])
        : "r"(a[0]), "r"(a[1]), "r"(a[2]), "r"(a[3]), "r"(b[0]), "r"(b[1]));
}

// ---------------- split helpers ----------------
__device__ __forceinline__ void f16_split1(float v, unsigned short& hb, unsigned short& lb) {
    __half h = __float2half_rn(v);
    float hf = __half2float(h);
    __half l = __float2half_rn(v - hf);
    hb = __half_as_ushort(h);
    lb = __half_as_ushort(l);
}
__device__ __forceinline__ void f16_split_store4(__half* ph, __half* pl, float4 v) {
    unsigned short h0, h1, h2, h3, l0, l1, l2, l3;
    f16_split1(v.x, h0, l0); f16_split1(v.y, h1, l1);
    f16_split1(v.z, h2, l2); f16_split1(v.w, h3, l3);
    *(uint2*)ph = make_uint2((uint32_t)h0 | ((uint32_t)h1 << 16), (uint32_t)h2 | ((uint32_t)h3 << 16));
    *(uint2*)pl = make_uint2((uint32_t)l0 | ((uint32_t)l1 << 16), (uint32_t)l2 | ((uint32_t)l3 << 16));
}
__device__ __forceinline__ void f16_store4(__half* p, float4 v) {
    __half2 a = __floats2half2_rn(v.x, v.y);
    __half2 b = __floats2half2_rn(v.z, v.w);
    *(uint2*)p = make_uint2(*(uint32_t*)&a, *(uint32_t*)&b);
}

// x: plain fp16 copy + interleaved fp16 x-slots of xxi
__global__ void split_kernel(const float* __restrict__ in, int n4) {
    int i = blockIdx.x * blockDim.x + threadIdx.x;
    if (i >= n4) return;
    float4 v = ((const float4*)in)[i];
    f16_store4(g_xf + (size_t)i * 4, v);
    int node = i >> 5;
    int c4 = i & 31;
    __half2 f0 = __floats2half2_rn(v.x, v.y);
    __half2 f1 = __floats2half2_rn(v.z, v.w);
    *(uint2*)(g_xxi + (size_t)node * 256 + c4 * 8) = make_uint2(*(uint32_t*)&f0, *(uint32_t*)&f1);
}

// Weights -> fp16 hi/lo pairs. float4 idx ranges:
// aff [0,4096) ih [4096,16384) hh [16384,28672) mg [28672,36864) w1 [36864,45056) w2 [45056,53248)
__global__ void split_weights_kernel(const float* __restrict__ Waff, const float* __restrict__ Wih,
                                     const float* __restrict__ Whh, const float* __restrict__ Wmg,
                                     const float* __restrict__ W1, const float* __restrict__ W2) {
    int i = blockIdx.x * blockDim.x + threadIdx.x;
    if (i >= 53248) return;
    const float* src; int base;
    if (i < 4096)       { src = Waff; base = 0; }
    else if (i < 16384) { src = Wih;  base = 4096; }
    else if (i < 28672) { src = Whh;  base = 16384; }
    else if (i < 36864) { src = Wmg;  base = 28672; }
    else if (i < 45056) { src = W1;   base = 36864; }
    else                { src = W2;   base = 45056; }
    float4 v = ((const float4*)src)[i - base];
    f16_split_store4(g_wf_h + (size_t)i * 4, g_wf_l + (size_t)i * 4, v);
}

// ---------------- init ----------------
__global__ void zero_init_kernel(int n) {
    int i = blockIdx.x * blockDim.x + threadIdx.x;
    if (i < n) g_cnt[i] = 0;
    if (i < 128) { g_bnsum[i] = 0.f; g_bnsq[i] = 0.f; }
}

// ---------------- CSR build ----------------
__global__ void count_kernel(const int* __restrict__ edges, int E) {
    int e = blockIdx.x * blockDim.x + threadIdx.x;
    if (e >= E) return;
    atomicAdd(&g_cnt[edges[E + e]], 1);
}
__global__ void scan1_kernel(int n) {
    __shared__ int sh[1024];
    int tid = threadIdx.x;
    int i = blockIdx.x * 1024 + tid;
    int v = (i < n) ? g_cnt[i] : 0;
    sh[tid] = v;
    __syncthreads();
    for (int off = 1; off < 1024; off <<= 1) {
        int t = (tid >= off) ? sh[tid - off] : 0;
        __syncthreads();
        sh[tid] += t;
        __syncthreads();
    }
    if (i < n) g_rowstart[i] = sh[tid] - v;
    if (tid == 1023) g_bsum[blockIdx.x] = sh[1023];
}
__global__ void scan2_kernel(int nb) {
    __shared__ int sh[128];
    int t = threadIdx.x;
    int v = (t < nb) ? g_bsum[t] : 0;
    sh[t] = v;
    __syncthreads();
    for (int off = 1; off < 128; off <<= 1) {
        int u = (t >= off) ? sh[t - off] : 0;
        __syncthreads();
        sh[t] += u;
        __syncthreads();
    }
    if (t < nb) g_boff[t] = sh[t] - v;
}
__global__ void scan3_kernel(int n) {
    int i = blockIdx.x * blockDim.x + threadIdx.x;
    if (i < n) {
        int v = g_rowstart[i] + g_boff[i >> 10];
        g_rowstart[i] = v;
        g_cursor[i] = v;
    }
}
__global__ void fill_kernel(const int* __restrict__ edges, int E) {
    int e = blockIdx.x * blockDim.x + threadIdx.x;
    if (e >= E) return;
    int src = edges[e];
    int dst = edges[E + e];
    int pos = atomicAdd(&g_cursor[dst], 1);
    g_col[pos] = src;
}

__device__ __forceinline__ uint32_t sw128(uint32_t r, uint32_t u) {
    return r * 128u + ((u ^ (r & 7u)) << 4);
}

// ---------------- fp16 GEMM: D = A_f16 @ (Bh[+Bl])^T + bias ----------------
// Bl==nullptr -> single-B (1 MMA/step). Stage layout fixed (48KB) in both modes.
// c16il: fp16 output goes to interleaved xxi layout (xi GEMM only).
#define STAGE2_BYTES 49152
#define GEMM2_SMEM (1024 + 2 * STAGE2_BYTES)

__global__ __launch_bounds__(256, 2)
void hmma_gemm_f16(const __half* __restrict__ A,
                   const __half* __restrict__ Bh, const __half* __restrict__ Bl,
                   const float* __restrict__ bias,
                   float* __restrict__ Cf, __half* __restrict__ Cf16, int c16il,
                   int M, int Ntot, int K, int relu, int bnred,
                   const float* __restrict__ resid, const float* __restrict__ eps_ptr)
{
    extern __shared__ char dsm[];
    uint32_t sb0 = smem_u32(dsm);
    uint32_t base0 = (sb0 + 1023u) & ~1023u;
    char* p0 = dsm + (base0 - sb0);

    int tid = threadIdx.x;
    int lane = tid & 31;
    int wid = tid >> 5;
    int wm = wid >> 2;
    int wn = wid & 3;
    int bm = blockIdx.y * 128, bn = blockIdx.x * 128;

    float acc[4][4][4];
#pragma unroll
    for (int i = 0; i < 4; i++)
#pragma unroll
        for (int j = 0; j < 4; j++)
#pragma unroll
            for (int k = 0; k < 4; k++) acc[i][j][k] = 0.f;

    const int NSt = K >> 6;

    auto load_stage = [&](int s) {
        uint32_t buf = base0 + (uint32_t)(s & 1) * STAGE2_BYTES;
        int kc = s * 64;
        // A tile: 128 rows x 8 units
#pragma unroll
        for (int i = 0; i < 4; i++) {
            int idx = tid + i * 256;
            uint32_t r = (uint32_t)(idx >> 3);
            uint32_t u = (uint32_t)(idx & 7);
            int gr = bm + (int)r; if (gr > M - 1) gr = M - 1;
            cpasync16(buf + sw128(r, u), A + (size_t)gr * K + kc + u * 8);
        }
        // Bh tile
#pragma unroll
        for (int i = 0; i < 4; i++) {
            int idx = tid + i * 256;
            uint32_t r = (uint32_t)(idx >> 3);
            uint32_t u = (uint32_t)(idx & 7);
            int gr = bn + (int)r; if (gr > Ntot - 1) gr = Ntot - 1;
            cpasync16(buf + 16384u + sw128(r, u), Bh + (size_t)gr * K + kc + u * 8);
        }
        // Bl tile (optional)
        if (Bl) {
#pragma unroll
            for (int i = 0; i < 4; i++) {
                int idx = tid + i * 256;
                uint32_t r = (uint32_t)(idx >> 3);
                uint32_t u = (uint32_t)(idx & 7);
                int gr = bn + (int)r; if (gr > Ntot - 1) gr = Ntot - 1;
                cpasync16(buf + 32768u + sw128(r, u), Bl + (size_t)gr * K + kc + u * 8);
            }
        }
        cp_commit();
    };

    load_stage(0);
    for (int s = 0; s < NSt; s++) {
        if (s + 1 < NSt) { load_stage(s + 1); cp_wait1(); }
        else cp_wait0();
        __syncthreads();
        uint32_t buf = base0 + (uint32_t)(s & 1) * STAGE2_BYTES;
#pragma unroll
        for (int ks = 0; ks < 4; ks++) {
            uint32_t bh[4][2], bl[4][2];
#pragma unroll
            for (int jp = 0; jp < 2; jp++) {
                uint32_t r = (uint32_t)(wn * 32 + jp * 16) + (uint32_t)(lane & 7) + (uint32_t)((lane >> 4) << 3);
                uint32_t u = (uint32_t)(ks * 2 + ((lane >> 3) & 1));
                uint32_t off = sw128(r, u);
                uint32_t t4[4];
                ldsm4(t4, buf + 16384u + off);
                bh[jp * 2][0] = t4[0]; bh[jp * 2][1] = t4[1];
                bh[jp * 2 + 1][0] = t4[2]; bh[jp * 2 + 1][1] = t4[3];
                if (Bl) {
                    ldsm4(t4, buf + 32768u + off);
                    bl[jp * 2][0] = t4[0]; bl[jp * 2][1] = t4[1];
                    bl[jp * 2 + 1][0] = t4[2]; bl[jp * 2 + 1][1] = t4[3];
                }
            }
#pragma unroll
            for (int mi = 0; mi < 4; mi++) {
                uint32_t r = (uint32_t)(wm * 64 + mi * 16) + (uint32_t)(lane & 15);
                uint32_t u = (uint32_t)(ks * 2 + (lane >> 4));
                uint32_t off = sw128(r, u);
                uint32_t af[4];
                ldsm4(af, buf + off);
#pragma unroll
                for (int ni = 0; ni < 4; ni++) {
                    mma_f16(acc[mi][ni], af, bh[ni]);
                    if (Bl) mma_f16(acc[mi][ni], af, bl[ni]);
                }
            }
        }
        __syncthreads();
    }

    // ---------------- epilogue ----------------
    float e = resid ? __ldg(eps_ptr) : 0.f;
    float cs[4][2], cq[4][2];
#pragma unroll
    for (int ni = 0; ni < 4; ni++) { cs[ni][0] = cs[ni][1] = cq[ni][0] = cq[ni][1] = 0.f; }

#pragma unroll
    for (int mi = 0; mi < 4; mi++) {
#pragma unroll
        for (int rr = 0; rr < 2; rr++) {
            int gr = bm + wm * 64 + mi * 16 + (lane >> 2) + rr * 8;
            if (gr >= M) continue;
#pragma unroll
            for (int ni = 0; ni < 4; ni++) {
                int gc = bn + wn * 32 + ni * 8 + (lane & 3) * 2;
                float v0 = acc[mi][ni][rr * 2 + 0];
                float v1 = acc[mi][ni][rr * 2 + 1];
                float2 bv = *(const float2*)(bias + gc);
                v0 += bv.x; v1 += bv.y;
                if (resid) {
                    float2 rv = *(const float2*)(resid + (size_t)gr * Ntot + gc);
                    v0 += e * rv.x; v1 += e * rv.y;
                }
                if (relu) { v0 = fmaxf(v0, 0.f); v1 = fmaxf(v1, 0.f); }
                if (bnred) {
                    cs[ni][0] += v0; cq[ni][0] += v0 * v0;
                    cs[ni][1] += v1; cq[ni][1] += v1 * v1;
                }
                if (Cf) {
                    *(float2*)(Cf + (size_t)gr * Ntot + gc) = make_float2(v0, v1);
                } else {
                    __half2 hv = __floats2half2_rn(v0, v1);
                    if (c16il) {
                        // interleaved xxi: xi pair at node*256 + (gc>>2)*8 + 4 + (gc&3)
                        *(uint32_t*)(Cf16 + (size_t)gr * 256 + ((gc >> 2) << 3) + 4 + (gc & 3)) =
                            *(uint32_t*)&hv;
                    } else {
                        *(uint32_t*)(Cf16 + (size_t)gr * Ntot + gc) = *(uint32_t*)&hv;
                    }
                }
            }
        }
    }

    if (bnred) {
        float* bsum = (float*)p0;
        float* bsq  = bsum + 128;
        __syncthreads();
        if (tid < 256) ((float*)p0)[tid] = 0.f;
        __syncthreads();
#pragma unroll
        for (int ni = 0; ni < 4; ni++) {
#pragma unroll
            for (int h = 0; h < 2; h++) {
                int col = wn * 32 + ni * 8 + (lane & 3) * 2 + h;
                atomicAdd(&bsum[col], cs[ni][h]);
                atomicAdd(&bsq[col], cq[ni][h]);
            }
        }
        __syncthreads();
        if (tid < 128) {
            int gc = bn + tid;
            atomicAdd(&g_bnsum[gc], bsum[tid]);
            atomicAdd(&g_bnsq[gc], bsq[tid]);
        }
    }
}

// ---------------- warp-per-node gather: one LDG.128/neighbor ----------------
__device__ __forceinline__ void acc_sm(float4& s, float4& m, uint4 u) {
    __half2 a = *(__half2*)&u.x, b = *(__half2*)&u.y;
    __half2 c = *(__half2*)&u.z, d = *(__half2*)&u.w;
    float2 f0 = __half22float2(a), f1 = __half22float2(b);
    float2 g0 = __half22float2(c), g1 = __half22float2(d);
    s.x += f0.x; s.y += f0.y; s.z += f1.x; s.w += f1.y;
    m.x = fmaxf(m.x, g0.x); m.y = fmaxf(m.y, g0.y);
    m.z = fmaxf(m.z, g1.x); m.w = fmaxf(m.w, g1.y);
}

__global__ void gather_reduce_kernel(int n) {
    int gt = blockIdx.x * blockDim.x + threadIdx.x;
    int node = gt >> 5;
    if (node >= n) return;
    int lane = gt & 31;
    int start = g_rowstart[node];
    int deg = g_cnt[node];
    float4 s = make_float4(0.f, 0.f, 0.f, 0.f);
    float4 m = make_float4(-1e30f, -1e30f, -1e30f, -1e30f);
    int j = 0;
    for (; j + 4 <= deg; j += 4) {
        int nb0 = g_col[start + j],     nb1 = g_col[start + j + 1];
        int nb2 = g_col[start + j + 2], nb3 = g_col[start + j + 3];
        uint4 u0 = __ldg((const uint4*)(g_xxi + (size_t)nb0 * 256) + lane);
        uint4 u1 = __ldg((const uint4*)(g_xxi + (size_t)nb1 * 256) + lane);
        uint4 u2 = __ldg((const uint4*)(g_xxi + (size_t)nb2 * 256) + lane);
        uint4 u3 = __ldg((const uint4*)(g_xxi + (size_t)nb3 * 256) + lane);
        acc_sm(s, m, u0); acc_sm(s, m, u1); acc_sm(s, m, u2); acc_sm(s, m, u3);
    }
    for (; j < deg; j++) {
        int nb = g_col[start + j];
        uint4 u = __ldg((const uint4*)(g_xxi + (size_t)nb * 256) + lane);
        acc_sm(s, m, u);
    }
    if (deg == 0) m = make_float4(0.f, 0.f, 0.f, 0.f);
    // agg_sum -> cat[:,0:128) fp16; agg_max -> am fp16 (exact: max of fp16 values)
    f16_store4(g_cat + (size_t)node * 256 + lane * 4, s);
    f16_store4(g_am + (size_t)node * 128 + lane * 4, m);
}

// ---------------- GRU cell elementwise (fp16 in, fp16 out) ----------------
__device__ __forceinline__ float gru1(float ir, float hr, float iz, float hz,
                                      float inn, float hn, float xv) {
    float r = 1.f / (1.f + expf(-(ir + hr)));
    float z = 1.f / (1.f + expf(-(iz + hz)));
    float nc = tanhf(inn + r * hn);
    return (1.f - z) * nc + z * xv;
}
__device__ __forceinline__ float4 ld_h4(const __half* p) {
    uint2 u = *(const uint2*)p;
    float2 a = __half22float2(*(__half2*)&u.x);
    float2 b = __half22float2(*(__half2*)&u.y);
    return make_float4(a.x, a.y, b.x, b.y);
}

__global__ void gru_kernel(const float* __restrict__ x, int M) {
    int idx = blockIdx.x * blockDim.x + threadIdx.x;
    if (idx >= M * 32) return;
    int node = idx >> 5;
    int c = (idx & 31) * 4;
    const __half* gi = g_gi + (size_t)node * 384;
    const __half* gh = g_gh + (size_t)node * 384;
    float4 ir = ld_h4(gi + c);
    float4 iz = ld_h4(gi + 128 + c);
    float4 in = ld_h4(gi + 256 + c);
    float4 hr = ld_h4(gh + c);
    float4 hz = ld_h4(gh + 128 + c);
    float4 hn = ld_h4(gh + 256 + c);
    float4 xv = *(const float4*)(x + (size_t)node * 128 + c);
    float4 o;
    o.x = gru1(ir.x, hr.x, iz.x, hz.x, in.x, hn.x, xv.x);
    o.y = gru1(ir.y, hr.y, iz.y, hz.y, in.y, hn.y, xv.y);
    o.z = gru1(ir.z, hr.z, iz.z, hz.z, in.z, hn.z, xv.z);
    o.w = gru1(ir.w, hr.w, iz.w, hz.w, in.w, hn.w, xv.w);
    f16_store4(g_cat + (size_t)node * 256 + 128 + c, o);
}

// ---------------- batchnorm normalize ----------------
__global__ void bn_norm_kernel(float* __restrict__ out, const float* __restrict__ gamma,
                               const float* __restrict__ beta, int M, float invM) {
    int idx = blockIdx.x * blockDim.x + threadIdx.x;
    if (idx >= M * 32) return;
    int node = idx >> 5;
    int c = (idx & 31) * 4;
    float4 v = *(float4*)(out + (size_t)node * 128 + c);
    float4 sm = *(const float4*)(g_bnsum + c);
    float4 sq = *(const float4*)(g_bnsq + c);
    float4 gm = *(const float4*)(gamma + c);
    float4 bt = *(const float4*)(beta + c);
    float4 o;
    { float mean = sm.x * invM, var = sq.x * invM - mean * mean;
      o.x = gm.x * (v.x - mean) * rsqrtf(var + 1e-5f) + bt.x; }
    { float mean = sm.y * invM, var = sq.y * invM - mean * mean;
      o.y = gm.y * (v.y - mean) * rsqrtf(var + 1e-5f) + bt.y; }
    { float mean = sm.z * invM, var = sq.z * invM - mean * mean;
      o.z = gm.z * (v.z - mean) * rsqrtf(var + 1e-5f) + bt.z; }
    { float mean = sm.w * invM, var = sq.w * invM - mean * mean;
      o.w = gm.w * (v.w - mean) * rsqrtf(var + 1e-5f) + bt.w; }
    *(float4*)(out + (size_t)node * 128 + c) = o;
}

// ---------------- launch ----------------
extern "C" void kernel_launch(void* const* d_in, const int* in_sizes, int n_in,
                              void* d_out, int out_size) {
    const float* x       = (const float*)d_in[0];
    const int*   edges   = (const int*)d_in[1];
    const float* W_aff   = (const float*)d_in[2];
    const float* b_aff   = (const float*)d_in[3];
    const float* W_ih    = (const float*)d_in[4];
    const float* b_ih    = (const float*)d_in[5];
    const float* W_hh    = (const float*)d_in[6];
    const float* b_hh    = (const float*)d_in[7];
    const float* W_merge = (const float*)d_in[8];
    const float* b_merge = (const float*)d_in[9];
    const float* eps     = (const float*)d_in[10];
    const float* W1      = (const float*)d_in[11];
    const float* b1      = (const float*)d_in[12];
    const float* W2      = (const float*)d_in[13];
    const float* b2      = (const float*)d_in[14];
    const float* gamma   = (const float*)d_in[15];
    const float* beta    = (const float*)d_in[16];
    float* out = (float*)d_out;

    int M = in_sizes[0] / 128;
    int E = in_sizes[1] / 2;

    __half *p_gh, *p_gi, *p_xxi, *p_xf, *p_am, *p_cat, *p_hf, *p_tf, *p_wfh, *p_wfl;
    cudaGetSymbolAddress((void**)&p_gh, g_gh);
    cudaGetSymbolAddress((void**)&p_gi, g_gi);
    cudaGetSymbolAddress((void**)&p_xxi, g_xxi);
    cudaGetSymbolAddress((void**)&p_xf, g_xf);
    cudaGetSymbolAddress((void**)&p_am, g_am);
    cudaGetSymbolAddress((void**)&p_cat, g_cat);
    cudaGetSymbolAddress((void**)&p_hf, g_hf);
    cudaGetSymbolAddress((void**)&p_tf, g_tf);
    cudaGetSymbolAddress((void**)&p_wfh, g_wf_h);
    cudaGetSymbolAddress((void**)&p_wfl, g_wf_l);

    cudaFuncSetAttribute(hmma_gemm_f16, cudaFuncAttributeMaxDynamicSharedMemorySize, GEMM2_SMEM);

    static cudaStream_t s1 = nullptr;
    static cudaEvent_t evR = nullptr, evCSR = nullptr, evXI = nullptr, evGH = nullptr;
    if (!s1) {
        cudaStreamCreateWithFlags(&s1, cudaStreamNonBlocking);
        cudaEventCreateWithFlags(&evR, cudaEventDisableTiming);
        cudaEventCreateWithFlags(&evCSR, cudaEventDisableTiming);
        cudaEventCreateWithFlags(&evXI, cudaEventDisableTiming);
        cudaEventCreateWithFlags(&evGH, cudaEventDisableTiming);
    }
    cudaStream_t s0 = 0;

    int mb = (M + 127) / 128;
    int nb = (M + 1023) / 1024;

    // root: zero counters (CSR count + BN accumulators)
    zero_init_kernel<<<(M + 255) / 256, 256, 0, s0>>>(M);
    cudaEventRecord(evR, s0);

    // ---- branch s1: CSR build ----
    cudaStreamWaitEvent(s1, evR, 0);
    count_kernel<<<(E + 255) / 256, 256, 0, s1>>>(edges, E);
    scan1_kernel<<<nb, 1024, 0, s1>>>(M);
    scan2_kernel<<<1, 128, 0, s1>>>(nb);
    scan3_kernel<<<(M + 255) / 256, 256, 0, s1>>>(M);
    fill_kernel<<<(E + 255) / 256, 256, 0, s1>>>(edges, E);
    cudaEventRecord(evCSR, s1);

    // ---- main stream: splits + xi GEMM ----
    {
        int n4 = M * 128 / 4;
        split_kernel<<<(n4 + 255) / 256, 256, 0, s0>>>(x, n4);
        split_weights_kernel<<<(53248 + 255) / 256, 256, 0, s0>>>(
            W_aff, W_ih, W_hh, W_merge, W1, W2);
    }
    // xi = x @ W_aff^T + b_aff -> interleaved fp16 (single-B; feeds damped GRU path)
    hmma_gemm_f16<<<dim3(1, mb), 256, GEMM2_SMEM, s0>>>(
        p_xf, p_wfh + F16_AFF, nullptr, b_aff,
        nullptr, p_xxi, 1, M, 128, 128, 0, 0, nullptr, nullptr);
    cudaEventRecord(evXI, s0);

    // ---- branch s1: gh GEMM (single-B fp16), concurrent with gather ----
    cudaStreamWaitEvent(s1, evXI, 0);
    hmma_gemm_f16<<<dim3(3, mb), 256, GEMM2_SMEM, s1>>>(
        p_xf, p_wfh + F16_HH, nullptr, b_hh,
        nullptr, p_gh, 0, M, 384, 128, 0, 0, nullptr, nullptr);
    cudaEventRecord(evGH, s1);

    // ---- main stream: gather (needs CSR + xxi) ----
    cudaStreamWaitEvent(s0, evCSR, 0);
    gather_reduce_kernel<<<(M * 32 + 255) / 256, 256, 0, s0>>>(M);

    // gi = agg_max @ W_ih^T + b_ih (single-B fp16; A exact fp16)
    hmma_gemm_f16<<<dim3(3, mb), 256, GEMM2_SMEM, s0>>>(
        p_am, p_wfh + F16_IH, nullptr, b_ih,
        nullptr, p_gi, 0, M, 384, 128, 0, 0, nullptr, nullptr);

    // GRU (needs gi + gh) -> cat[:, 128:)
    cudaStreamWaitEvent(s0, evGH, 0);
    gru_kernel<<<(M * 32 + 255) / 256, 256, 0, s0>>>(x, M);

    // h = cat @ W_merge^T + b_merge + eps*x (2-term, fp16 out)
    hmma_gemm_f16<<<dim3(1, mb), 256, GEMM2_SMEM, s0>>>(
        p_cat, p_wfh + F16_MG, p_wfl + F16_MG, b_merge,
        nullptr, p_hf, 0, M, 128, 256, 0, 0, x, eps);

    // t = relu(h @ W1^T + b1) (2-term, fp16 out)
    hmma_gemm_f16<<<dim3(2, mb), 256, GEMM2_SMEM, s0>>>(
        p_hf, p_wfh + F16_W1, p_wfl + F16_W1, b1,
        nullptr, p_tf, 0, M, 256, 128, 1, 0, nullptr, nullptr);

    // out = relu(t @ W2^T + b2) (fp32 -> d_out) + fused BN reduce (2-term)
    hmma_gemm_f16<<<dim3(1, mb), 256, GEMM2_SMEM, s0>>>(
        p_tf, p_wfh + F16_W2, p_wfl + F16_W2, b2,
        out, nullptr, 0, M, 128, 256, 1, 1, nullptr, nullptr);

    // batchnorm normalize (train mode, biased variance)
    bn_norm_kernel<<<(M * 32 + 255) / 256, 256, 0, s0>>>(out, gamma, beta, M, 1.0f / (float)M);
}

// round 15
// speedup vs baseline: 1.4172x; 1.0343x over previous
#include <cuda_runtime.h>
#include <cuda_fp16.h>
#include <math.h>
#include <stdint.h>

// ---------------- problem-size constants ----------------
#define NMAX 100000
#define EMAX 1600000

// ---------------- device scratch ----------------
__device__ __align__(16) __half g_gh[(size_t)NMAX * 384];   // fp16: x @ W_hh^T + b_hh
__device__ __align__(16) __half g_gi[(size_t)NMAX * 384];   // fp16: agg_max @ W_ih^T + b_ih
__device__ __align__(16) __half g_xxi[(size_t)NMAX * 256];  // interleaved fp16 [x4|xi4] (gather)
__device__ __align__(16) __half g_xf[(size_t)NMAX * 128];   // plain fp16 x (xi/gh A-side, gru)
__device__ __align__(16) __half g_am[(size_t)NMAX * 128];   // fp16 agg_max (exact)
__device__ __align__(16) __half g_cat[(size_t)NMAX * 256];  // fp16 [agg_sum | rnn_out]
__device__ __align__(16) __half g_hf[(size_t)NMAX * 128];   // fp16 merge out
__device__ __align__(16) __half g_tf[(size_t)NMAX * 256];   // fp16 relu(W1...)

__device__ __align__(16) __half g_wf_h[212992];  // fp16 weight hi (aff,ih,hh,mg,w1,w2)
__device__ __align__(16) __half g_wf_l[212992];  // fp16 weight lo

__device__ int g_cnt[NMAX];
__device__ int g_rowstart[NMAX];
__device__ int g_cursor[NMAX];
__device__ int g_col[EMAX];
__device__ int g_bsum[256];
__device__ int g_boff[256];
__device__ float g_bnsum[128];
__device__ float g_bnsq[128];

// fp16 weight offsets (elements)
#define F16_AFF 0
#define F16_IH  16384
#define F16_HH  65536
#define F16_MG  114688
#define F16_W1  147456
#define F16_W2  180224

// ---------------- low-level helpers (plain sm_80-class PTX) ----------------
__device__ __forceinline__ uint32_t smem_u32(const void* p) {
    uint32_t a;
    asm("{ .reg .u64 t; cvta.to.shared.u64 t, %1; cvt.u32.u64 %0, t; }" : "=r"(a) : "l"(p));
    return a;
}
__device__ __forceinline__ void cpasync16(uint32_t dst, const void* src) {
    asm volatile("cp.async.cg.shared.global [%0], [%1], 16;" :: "r"(dst), "l"(src));
}
__device__ __forceinline__ void cp_commit() {
    asm volatile("cp.async.commit_group;" ::: "memory");
}
__device__ __forceinline__ void cp_wait1() {
    asm volatile("cp.async.wait_group 1;" ::: "memory");
}
__device__ __forceinline__ void cp_wait0() {
    asm volatile("cp.async.wait_group 0;" ::: "memory");
}
__device__ __forceinline__ void ldsm4(uint32_t* r, uint32_t addr) {
    asm volatile("ldmatrix.sync.aligned.m8n8.x4.shared.b16 {%0,%1,%2,%3}, [%4];"
                 : "=r"(r[0]), "=r"(r[1]), "=r"(r[2]), "=r"(r[3]) : "r"(addr));
}
__device__ __forceinline__ void mma_f16(float* d, const uint32_t* a, const uint32_t* b) {
    asm volatile(
        "mma.sync.aligned.m16n8k16.row.col.f32.f16.f16.f32 "
        "{%0,%1,%2,%3}, {%4,%5,%6,%7}, {%8,%9}, {%0,%1,%2,%3};"
        : "+f"(d[0]), "+f"(d[1]), "+f"(d[2]), "+f"(d[3])
        : "r"(a[0]), "r"(a[1]), "r"(a[2]), "r"(a[3]), "r"(b[0]), "r"(b[1]));
}

// ---------------- split helpers ----------------
__device__ __forceinline__ void f16_split1(float v, unsigned short& hb, unsigned short& lb) {
    __half h = __float2half_rn(v);
    float hf = __half2float(h);
    __half l = __float2half_rn(v - hf);
    hb = __half_as_ushort(h);
    lb = __half_as_ushort(l);
}
__device__ __forceinline__ void f16_split_store4(__half* ph, __half* pl, float4 v) {
    unsigned short h0, h1, h2, h3, l0, l1, l2, l3;
    f16_split1(v.x, h0, l0); f16_split1(v.y, h1, l1);
    f16_split1(v.z, h2, l2); f16_split1(v.w, h3, l3);
    *(uint2*)ph = make_uint2((uint32_t)h0 | ((uint32_t)h1 << 16), (uint32_t)h2 | ((uint32_t)h3 << 16));
    *(uint2*)pl = make_uint2((uint32_t)l0 | ((uint32_t)l1 << 16), (uint32_t)l2 | ((uint32_t)l3 << 16));
}
__device__ __forceinline__ void f16_store4(__half* p, float4 v) {
    __half2 a = __floats2half2_rn(v.x, v.y);
    __half2 b = __floats2half2_rn(v.z, v.w);
    *(uint2*)p = make_uint2(*(uint32_t*)&a, *(uint32_t*)&b);
}

// Combined split: idx [0,n4) -> x (fp16 copy + interleaved xxi x-slots);
// idx [n4, n4+53248) -> weights (fp16 hi/lo pair).
__global__ void split_all_kernel(const float* __restrict__ in, int n4,
                                 const float* __restrict__ Waff, const float* __restrict__ Wih,
                                 const float* __restrict__ Whh, const float* __restrict__ Wmg,
                                 const float* __restrict__ W1, const float* __restrict__ W2) {
    int i = blockIdx.x * blockDim.x + threadIdx.x;
    if (i < n4) {
        float4 v = ((const float4*)in)[i];
        f16_store4(g_xf + (size_t)i * 4, v);
        int node = i >> 5;
        int c4 = i & 31;
        __half2 f0 = __floats2half2_rn(v.x, v.y);
        __half2 f1 = __floats2half2_rn(v.z, v.w);
        *(uint2*)(g_xxi + (size_t)node * 256 + c4 * 8) = make_uint2(*(uint32_t*)&f0, *(uint32_t*)&f1);
        return;
    }
    int w = i - n4;
    if (w >= 53248) return;
    const float* src; int base;
    if (w < 4096)       { src = Waff; base = 0; }
    else if (w < 16384) { src = Wih;  base = 4096; }
    else if (w < 28672) { src = Whh;  base = 16384; }
    else if (w < 36864) { src = Wmg;  base = 28672; }
    else if (w < 45056) { src = W1;   base = 36864; }
    else                { src = W2;   base = 45056; }
    float4 v = ((const float4*)src)[w - base];
    f16_split_store4(g_wf_h + (size_t)w * 4, g_wf_l + (size_t)w * 4, v);
}

// ---------------- init ----------------
__global__ void zero_init_kernel(int n) {
    int i = blockIdx.x * blockDim.x + threadIdx.x;
    if (i < n) g_cnt[i] = 0;
    if (i < 128) { g_bnsum[i] = 0.f; g_bnsq[i] = 0.f; }
}

// ---------------- CSR build ----------------
__global__ void count_kernel(const int* __restrict__ edges, int E) {
    int e = blockIdx.x * blockDim.x + threadIdx.x;
    if (e >= E) return;
    atomicAdd(&g_cnt[edges[E + e]], 1);
}
__global__ void scan1_kernel(int n) {
    __shared__ int sh[1024];
    int tid = threadIdx.x;
    int i = blockIdx.x * 1024 + tid;
    int v = (i < n) ? g_cnt[i] : 0;
    sh[tid] = v;
    __syncthreads();
    for (int off = 1; off < 1024; off <<= 1) {
        int t = (tid >= off) ? sh[tid - off] : 0;
        __syncthreads();
        sh[tid] += t;
        __syncthreads();
    }
    if (i < n) g_rowstart[i] = sh[tid] - v;
    if (tid == 1023) g_bsum[blockIdx.x] = sh[1023];
}
__global__ void scan2_kernel(int nb) {
    __shared__ int sh[128];
    int t = threadIdx.x;
    int v = (t < nb) ? g_bsum[t] : 0;
    sh[t] = v;
    __syncthreads();
    for (int off = 1; off < 128; off <<= 1) {
        int u = (t >= off) ? sh[t - off] : 0;
        __syncthreads();
        sh[t] += u;
        __syncthreads();
    }
    if (t < nb) g_boff[t] = sh[t] - v;
}
__global__ void scan3_kernel(int n) {
    int i = blockIdx.x * blockDim.x + threadIdx.x;
    if (i < n) {
        int v = g_rowstart[i] + g_boff[i >> 10];
        g_rowstart[i] = v;
        g_cursor[i] = v;
    }
}
__global__ void fill_kernel(const int* __restrict__ edges, int E) {
    int e = blockIdx.x * blockDim.x + threadIdx.x;
    if (e >= E) return;
    int src = edges[e];
    int dst = edges[E + e];
    int pos = atomicAdd(&g_cursor[dst], 1);
    g_col[pos] = src;
}

__device__ __forceinline__ uint32_t sw128(uint32_t r, uint32_t u) {
    return r * 128u + ((u ^ (r & 7u)) << 4);
}

// ---------------- fp16 GEMM: D = A_f16 @ (Bh[+Bl])^T + bias ----------------
// Bl==nullptr -> single-B (1 MMA/step). Stage layout fixed (48KB) in both modes.
// c16il: fp16 output goes to interleaved xxi layout (xi GEMM only).
#define STAGE2_BYTES 49152
#define GEMM2_SMEM (1024 + 2 * STAGE2_BYTES)

__global__ __launch_bounds__(256, 2)
void hmma_gemm_f16(const __half* __restrict__ A,
                   const __half* __restrict__ Bh, const __half* __restrict__ Bl,
                   const float* __restrict__ bias,
                   float* __restrict__ Cf, __half* __restrict__ Cf16, int c16il,
                   int M, int Ntot, int K, int relu, int bnred,
                   const float* __restrict__ resid, const float* __restrict__ eps_ptr)
{
    extern __shared__ char dsm[];
    uint32_t sb0 = smem_u32(dsm);
    uint32_t base0 = (sb0 + 1023u) & ~1023u;
    char* p0 = dsm + (base0 - sb0);

    int tid = threadIdx.x;
    int lane = tid & 31;
    int wid = tid >> 5;
    int wm = wid >> 2;
    int wn = wid & 3;
    int bm = blockIdx.y * 128, bn = blockIdx.x * 128;

    float acc[4][4][4];
#pragma unroll
    for (int i = 0; i < 4; i++)
#pragma unroll
        for (int j = 0; j < 4; j++)
#pragma unroll
            for (int k = 0; k < 4; k++) acc[i][j][k] = 0.f;

    const int NSt = K >> 6;

    auto load_stage = [&](int s) {
        uint32_t buf = base0 + (uint32_t)(s & 1) * STAGE2_BYTES;
        int kc = s * 64;
#pragma unroll
        for (int i = 0; i < 4; i++) {
            int idx = tid + i * 256;
            uint32_t r = (uint32_t)(idx >> 3);
            uint32_t u = (uint32_t)(idx & 7);
            int gr = bm + (int)r; if (gr > M - 1) gr = M - 1;
            cpasync16(buf + sw128(r, u), A + (size_t)gr * K + kc + u * 8);
        }
#pragma unroll
        for (int i = 0; i < 4; i++) {
            int idx = tid + i * 256;
            uint32_t r = (uint32_t)(idx >> 3);
            uint32_t u = (uint32_t)(idx & 7);
            int gr = bn + (int)r; if (gr > Ntot - 1) gr = Ntot - 1;
            cpasync16(buf + 16384u + sw128(r, u), Bh + (size_t)gr * K + kc + u * 8);
        }
        if (Bl) {
#pragma unroll
            for (int i = 0; i < 4; i++) {
                int idx = tid + i * 256;
                uint32_t r = (uint32_t)(idx >> 3);
                uint32_t u = (uint32_t)(idx & 7);
                int gr = bn + (int)r; if (gr > Ntot - 1) gr = Ntot - 1;
                cpasync16(buf + 32768u + sw128(r, u), Bl + (size_t)gr * K + kc + u * 8);
            }
        }
        cp_commit();
    };

    load_stage(0);
    for (int s = 0; s < NSt; s++) {
        if (s + 1 < NSt) { load_stage(s + 1); cp_wait1(); }
        else cp_wait0();
        __syncthreads();
        uint32_t buf = base0 + (uint32_t)(s & 1) * STAGE2_BYTES;
#pragma unroll
        for (int ks = 0; ks < 4; ks++) {
            uint32_t bh[4][2], bl[4][2];
#pragma unroll
            for (int jp = 0; jp < 2; jp++) {
                uint32_t r = (uint32_t)(wn * 32 + jp * 16) + (uint32_t)(lane & 7) + (uint32_t)((lane >> 4) << 3);
                uint32_t u = (uint32_t)(ks * 2 + ((lane >> 3) & 1));
                uint32_t off = sw128(r, u);
                uint32_t t4[4];
                ldsm4(t4, buf + 16384u + off);
                bh[jp * 2][0] = t4[0]; bh[jp * 2][1] = t4[1];
                bh[jp * 2 + 1][0] = t4[2]; bh[jp * 2 + 1][1] = t4[3];
                if (Bl) {
                    ldsm4(t4, buf + 32768u + off);
                    bl[jp * 2][0] = t4[0]; bl[jp * 2][1] = t4[1];
                    bl[jp * 2 + 1][0] = t4[2]; bl[jp * 2 + 1][1] = t4[3];
                }
            }
#pragma unroll
            for (int mi = 0; mi < 4; mi++) {
                uint32_t r = (uint32_t)(wm * 64 + mi * 16) + (uint32_t)(lane & 15);
                uint32_t u = (uint32_t)(ks * 2 + (lane >> 4));
                uint32_t off = sw128(r, u);
                uint32_t af[4];
                ldsm4(af, buf + off);
#pragma unroll
                for (int ni = 0; ni < 4; ni++) {
                    mma_f16(acc[mi][ni], af, bh[ni]);
                    if (Bl) mma_f16(acc[mi][ni], af, bl[ni]);
                }
            }
        }
        __syncthreads();
    }

    // ---------------- epilogue ----------------
    float e = resid ? __ldg(eps_ptr) : 0.f;
    float cs[4][2], cq[4][2];
#pragma unroll
    for (int ni = 0; ni < 4; ni++) { cs[ni][0] = cs[ni][1] = cq[ni][0] = cq[ni][1] = 0.f; }

#pragma unroll
    for (int mi = 0; mi < 4; mi++) {
#pragma unroll
        for (int rr = 0; rr < 2; rr++) {
            int gr = bm + wm * 64 + mi * 16 + (lane >> 2) + rr * 8;
            if (gr >= M) continue;
#pragma unroll
            for (int ni = 0; ni < 4; ni++) {
                int gc = bn + wn * 32 + ni * 8 + (lane & 3) * 2;
                float v0 = acc[mi][ni][rr * 2 + 0];
                float v1 = acc[mi][ni][rr * 2 + 1];
                float2 bv = *(const float2*)(bias + gc);
                v0 += bv.x; v1 += bv.y;
                if (resid) {
                    float2 rv = *(const float2*)(resid + (size_t)gr * Ntot + gc);
                    v0 += e * rv.x; v1 += e * rv.y;
                }
                if (relu) { v0 = fmaxf(v0, 0.f); v1 = fmaxf(v1, 0.f); }
                if (bnred) {
                    cs[ni][0] += v0; cq[ni][0] += v0 * v0;
                    cs[ni][1] += v1; cq[ni][1] += v1 * v1;
                }
                if (Cf) {
                    *(float2*)(Cf + (size_t)gr * Ntot + gc) = make_float2(v0, v1);
                } else {
                    __half2 hv = __floats2half2_rn(v0, v1);
                    if (c16il) {
                        // interleaved xxi: xi pair at node*256 + (gc>>2)*8 + 4 + (gc&3)
                        *(uint32_t*)(Cf16 + (size_t)gr * 256 + ((gc >> 2) << 3) + 4 + (gc & 3)) =
                            *(uint32_t*)&hv;
                    } else {
                        *(uint32_t*)(Cf16 + (size_t)gr * Ntot + gc) = *(uint32_t*)&hv;
                    }
                }
            }
        }
    }

    if (bnred) {
        float* bsum = (float*)p0;
        float* bsq  = bsum + 128;
        __syncthreads();
        if (tid < 256) ((float*)p0)[tid] = 0.f;
        __syncthreads();
#pragma unroll
        for (int ni = 0; ni < 4; ni++) {
#pragma unroll
            for (int h = 0; h < 2; h++) {
                int col = wn * 32 + ni * 8 + (lane & 3) * 2 + h;
                atomicAdd(&bsum[col], cs[ni][h]);
                atomicAdd(&bsq[col], cq[ni][h]);
            }
        }
        __syncthreads();
        if (tid < 128) {
            int gc = bn + tid;
            atomicAdd(&g_bnsum[gc], bsum[tid]);
            atomicAdd(&g_bnsq[gc], bsq[tid]);
        }
    }
}

// ---------------- warp-per-node gather: one LDG.128/neighbor ----------------
__device__ __forceinline__ void acc_sm(float4& s, float4& m, uint4 u) {
    __half2 a = *(__half2*)&u.x, b = *(__half2*)&u.y;
    __half2 c = *(__half2*)&u.z, d = *(__half2*)&u.w;
    float2 f0 = __half22float2(a), f1 = __half22float2(b);
    float2 g0 = __half22float2(c), g1 = __half22float2(d);
    s.x += f0.x; s.y += f0.y; s.z += f1.x; s.w += f1.y;
    m.x = fmaxf(m.x, g0.x); m.y = fmaxf(m.y, g0.y);
    m.z = fmaxf(m.z, g1.x); m.w = fmaxf(m.w, g1.y);
}

__global__ void gather_reduce_kernel(int n) {
    int gt = blockIdx.x * blockDim.x + threadIdx.x;
    int node = gt >> 5;
    if (node >= n) return;
    int lane = gt & 31;
    int start = g_rowstart[node];
    int deg = g_cnt[node];
    float4 s = make_float4(0.f, 0.f, 0.f, 0.f);
    float4 m = make_float4(-1e30f, -1e30f, -1e30f, -1e30f);
    int j = 0;
    for (; j + 4 <= deg; j += 4) {
        int nb0 = g_col[start + j],     nb1 = g_col[start + j + 1];
        int nb2 = g_col[start + j + 2], nb3 = g_col[start + j + 3];
        uint4 u0 = __ldg((const uint4*)(g_xxi + (size_t)nb0 * 256) + lane);
        uint4 u1 = __ldg((const uint4*)(g_xxi + (size_t)nb1 * 256) + lane);
        uint4 u2 = __ldg((const uint4*)(g_xxi + (size_t)nb2 * 256) + lane);
        uint4 u3 = __ldg((const uint4*)(g_xxi + (size_t)nb3 * 256) + lane);
        acc_sm(s, m, u0); acc_sm(s, m, u1); acc_sm(s, m, u2); acc_sm(s, m, u3);
    }
    for (; j < deg; j++) {
        int nb = g_col[start + j];
        uint4 u = __ldg((const uint4*)(g_xxi + (size_t)nb * 256) + lane);
        acc_sm(s, m, u);
    }
    if (deg == 0) m = make_float4(0.f, 0.f, 0.f, 0.f);
    // agg_sum -> cat[:,0:128) fp16; agg_max -> am fp16 (exact: max of fp16 values)
    f16_store4(g_cat + (size_t)node * 256 + lane * 4, s);
    f16_store4(g_am + (size_t)node * 128 + lane * 4, m);
}

// ---------------- GRU cell elementwise (fp16 in, fp16 out) ----------------
__device__ __forceinline__ float gru1(float ir, float hr, float iz, float hz,
                                      float inn, float hn, float xv) {
    float r = 1.f / (1.f + expf(-(ir + hr)));
    float z = 1.f / (1.f + expf(-(iz + hz)));
    float nc = tanhf(inn + r * hn);
    return (1.f - z) * nc + z * xv;
}
__device__ __forceinline__ float4 ld_h4(const __half* p) {
    uint2 u = *(const uint2*)p;
    float2 a = __half22float2(*(__half2*)&u.x);
    float2 b = __half22float2(*(__half2*)&u.y);
    return make_float4(a.x, a.y, b.x, b.y);
}

__global__ void gru_kernel(int M) {
    int idx = blockIdx.x * blockDim.x + threadIdx.x;
    if (idx >= M * 32) return;
    int node = idx >> 5;
    int c = (idx & 31) * 4;
    const __half* gi = g_gi + (size_t)node * 384;
    const __half* gh = g_gh + (size_t)node * 384;
    float4 ir = ld_h4(gi + c);
    float4 iz = ld_h4(gi + 128 + c);
    float4 in = ld_h4(gi + 256 + c);
    float4 hr = ld_h4(gh + c);
    float4 hz = ld_h4(gh + 128 + c);
    float4 hn = ld_h4(gh + 256 + c);
    float4 xv = ld_h4(g_xf + (size_t)node * 128 + c);   // fp16 x (same quant class as cat store)
    float4 o;
    o.x = gru1(ir.x, hr.x, iz.x, hz.x, in.x, hn.x, xv.x);
    o.y = gru1(ir.y, hr.y, iz.y, hz.y, in.y, hn.y, xv.y);
    o.z = gru1(ir.z, hr.z, iz.z, hz.z, in.z, hn.z, xv.z);
    o.w = gru1(ir.w, hr.w, iz.w, hz.w, in.w, hn.w, xv.w);
    f16_store4(g_cat + (size_t)node * 256 + 128 + c, o);
}

// ---------------- batchnorm normalize ----------------
__global__ void bn_norm_kernel(float* __restrict__ out, const float* __restrict__ gamma,
                               const float* __restrict__ beta, int M, float invM) {
    int idx = blockIdx.x * blockDim.x + threadIdx.x;
    if (idx >= M * 32) return;
    int node = idx >> 5;
    int c = (idx & 31) * 4;
    float4 v = *(float4*)(out + (size_t)node * 128 + c);
    float4 sm = *(const float4*)(g_bnsum + c);
    float4 sq = *(const float4*)(g_bnsq + c);
    float4 gm = *(const float4*)(gamma + c);
    float4 bt = *(const float4*)(beta + c);
    float4 o;
    { float mean = sm.x * invM, var = sq.x * invM - mean * mean;
      o.x = gm.x * (v.x - mean) * rsqrtf(var + 1e-5f) + bt.x; }
    { float mean = sm.y * invM, var = sq.y * invM - mean * mean;
      o.y = gm.y * (v.y - mean) * rsqrtf(var + 1e-5f) + bt.y; }
    { float mean = sm.z * invM, var = sq.z * invM - mean * mean;
      o.z = gm.z * (v.z - mean) * rsqrtf(var + 1e-5f) + bt.z; }
    { float mean = sm.w * invM, var = sq.w * invM - mean * mean;
      o.w = gm.w * (v.w - mean) * rsqrtf(var + 1e-5f) + bt.w; }
    *(float4*)(out + (size_t)node * 128 + c) = o;
}

// ---------------- launch ----------------
extern "C" void kernel_launch(void* const* d_in, const int* in_sizes, int n_in,
                              void* d_out, int out_size) {
    const float* x       = (const float*)d_in[0];
    const int*   edges   = (const int*)d_in[1];
    const float* W_aff   = (const float*)d_in[2];
    const float* b_aff   = (const float*)d_in[3];
    const float* W_ih    = (const float*)d_in[4];
    const float* b_ih    = (const float*)d_in[5];
    const float* W_hh    = (const float*)d_in[6];
    const float* b_hh    = (const float*)d_in[7];
    const float* W_merge = (const float*)d_in[8];
    const float* b_merge = (const float*)d_in[9];
    const float* eps     = (const float*)d_in[10];
    const float* W1      = (const float*)d_in[11];
    const float* b1      = (const float*)d_in[12];
    const float* W2      = (const float*)d_in[13];
    const float* b2      = (const float*)d_in[14];
    const float* gamma   = (const float*)d_in[15];
    const float* beta    = (const float*)d_in[16];
    float* out = (float*)d_out;

    int M = in_sizes[0] / 128;
    int E = in_sizes[1] / 2;

    __half *p_gh, *p_gi, *p_xxi, *p_xf, *p_am, *p_cat, *p_hf, *p_tf, *p_wfh, *p_wfl;
    cudaGetSymbolAddress((void**)&p_gh, g_gh);
    cudaGetSymbolAddress((void**)&p_gi, g_gi);
    cudaGetSymbolAddress((void**)&p_xxi, g_xxi);
    cudaGetSymbolAddress((void**)&p_xf, g_xf);
    cudaGetSymbolAddress((void**)&p_am, g_am);
    cudaGetSymbolAddress((void**)&p_cat, g_cat);
    cudaGetSymbolAddress((void**)&p_hf, g_hf);
    cudaGetSymbolAddress((void**)&p_tf, g_tf);
    cudaGetSymbolAddress((void**)&p_wfh, g_wf_h);
    cudaGetSymbolAddress((void**)&p_wfl, g_wf_l);

    cudaFuncSetAttribute(hmma_gemm_f16, cudaFuncAttributeMaxDynamicSharedMemorySize, GEMM2_SMEM);

    static cudaStream_t s1 = nullptr;
    static cudaEvent_t evR = nullptr, evCSR = nullptr, evXI = nullptr, evGH = nullptr;
    if (!s1) {
        cudaStreamCreateWithFlags(&s1, cudaStreamNonBlocking);
        cudaEventCreateWithFlags(&evR, cudaEventDisableTiming);
        cudaEventCreateWithFlags(&evCSR, cudaEventDisableTiming);
        cudaEventCreateWithFlags(&evXI, cudaEventDisableTiming);
        cudaEventCreateWithFlags(&evGH, cudaEventDisableTiming);
    }
    cudaStream_t s0 = 0;

    int mb = (M + 127) / 128;
    int nb = (M + 1023) / 1024;

    // Fork s1 from the capture-origin stream BEFORE any s1 work (capture-legal):
    // event node depends only on capture-begin, so s1's chain runs fully parallel to s0.
    cudaEventRecord(evR, s0);
    cudaStreamWaitEvent(s1, evR, 0);

    // ---- branch s1: zero + CSR build (zero also clears BN sums; consumed on s0
    //      only after the evCSR-ordered gather) ----
    zero_init_kernel<<<(M + 255) / 256, 256, 0, s1>>>(M);
    count_kernel<<<(E + 255) / 256, 256, 0, s1>>>(edges, E);
    scan1_kernel<<<nb, 1024, 0, s1>>>(M);
    scan2_kernel<<<1, 128, 0, s1>>>(nb);
    scan3_kernel<<<(M + 255) / 256, 256, 0, s1>>>(M);
    fill_kernel<<<(E + 255) / 256, 256, 0, s1>>>(edges, E);
    cudaEventRecord(evCSR, s1);

    // ---- main stream: combined split + xi GEMM ----
    {
        int n4 = M * 128 / 4;
        int tot = n4 + 53248;
        split_all_kernel<<<(tot + 255) / 256, 256, 0, s0>>>(
            x, n4, W_aff, W_ih, W_hh, W_merge, W1, W2);
    }
    // xi = x @ W_aff^T + b_aff -> interleaved fp16 (single-B; feeds damped GRU path)
    hmma_gemm_f16<<<dim3(1, mb), 256, GEMM2_SMEM, s0>>>(
        p_xf, p_wfh + F16_AFF, nullptr, b_aff,
        nullptr, p_xxi, 1, M, 128, 128, 0, 0, nullptr, nullptr);
    cudaEventRecord(evXI, s0);

    // ---- branch s1: gh GEMM (single-B fp16), concurrent with gather ----
    cudaStreamWaitEvent(s1, evXI, 0);
    hmma_gemm_f16<<<dim3(3, mb), 256, GEMM2_SMEM, s1>>>(
        p_xf, p_wfh + F16_HH, nullptr, b_hh,
        nullptr, p_gh, 0, M, 384, 128, 0, 0, nullptr, nullptr);
    cudaEventRecord(evGH, s1);

    // ---- main stream: gather (needs CSR + xxi) ----
    cudaStreamWaitEvent(s0, evCSR, 0);
    gather_reduce_kernel<<<(M * 32 + 255) / 256, 256, 0, s0>>>(M);

    // gi = agg_max @ W_ih^T + b_ih (single-B fp16; A exact fp16)
    hmma_gemm_f16<<<dim3(3, mb), 256, GEMM2_SMEM, s0>>>(
        p_am, p_wfh + F16_IH, nullptr, b_ih,
        nullptr, p_gi, 0, M, 384, 128, 0, 0, nullptr, nullptr);

    // GRU (needs gi + gh) -> cat[:, 128:)
    cudaStreamWaitEvent(s0, evGH, 0);
    gru_kernel<<<(M * 32 + 255) / 256, 256, 0, s0>>>(M);

    // h = cat @ W_merge^T + b_merge + eps*x (2-term, fp16 out)
    hmma_gemm_f16<<<dim3(1, mb), 256, GEMM2_SMEM, s0>>>(
        p_cat, p_wfh + F16_MG, p_wfl + F16_MG, b_merge,
        nullptr, p_hf, 0, M, 128, 256, 0, 0, x, eps);

    // t = relu(h @ W1^T + b1) (2-term, fp16 out)
    hmma_gemm_f16<<<dim3(2, mb), 256, GEMM2_SMEM, s0>>>(
        p_hf, p_wfh + F16_W1, p_wfl + F16_W1, b1,
        nullptr, p_tf, 0, M, 256, 128, 1, 0, nullptr, nullptr);

    // out = relu(t @ W2^T + b2) (fp32 -> d_out) + fused BN reduce (2-term)
    hmma_gemm_f16<<<dim3(1, mb), 256, GEMM2_SMEM, s0>>>(
        p_tf, p_wfh + F16_W2, p_wfl + F16_W2, b2,
        out, nullptr, 0, M, 128, 256, 1, 1, nullptr, nullptr);

    // batchnorm normalize (train mode, biased variance)
    bn_norm_kernel<<<(M * 32 + 255) / 256, 256, 0, s0>>>(out, gamma, beta, M, 1.0f / (float)M);
}